// round 1
// baseline (speedup 1.0000x reference)
#include <cuda_runtime.h>
#include <cstdint>

// ---- problem dims (fixed by the dataset) ----
#define Bv   8
#define Tv   1024
#define Dv   512
#define Hv   8
#define HDv  64
#define D2v  1024   // concat channels

// ---- scratch (device globals; no allocation allowed) ----
__device__ float g_q[Bv * Tv * Dv];
__device__ float g_k[Bv * Tv * Dv];
__device__ float g_v[Bv * Tv * Dv];
__device__ float g_val[Bv * Tv * D2v];          // [B, T, 2D] concat buffer
__device__ float g_wq[3 * Dv * Dv];             // repacked: [3*Cin, Cout]
__device__ float g_wk[3 * Dv * Dv];
__device__ float g_wv[3 * Dv * Dv];
__device__ float g_w2[3 * D2v * Dv];

// ============================================================
// Weight repack: w[co, ci, k] -> wp[(k*cin + ci)*512 + co]
// ============================================================
__global__ void repack_w(const float* __restrict__ w, float* __restrict__ wp, int cin) {
    int idx = blockIdx.x * 256 + threadIdx.x;
    int total = 3 * cin * Dv;
    if (idx >= total) return;
    int co = idx & (Dv - 1);
    int r  = idx >> 9;
    int ci = r % cin;
    int k  = r / cin;
    wp[idx] = w[((size_t)co * cin + ci) * 3 + k];
}

// ============================================================
// Fused conv1d(k=3, same) + bias + ReLU as tiled GEMM.
// Y[b,t,co] = relu(bias[co] + sum_k sum_ci X[b,t+k-1,ci] * Wp[k*CIN+ci, co])
// Tiles: 64(t) x 64(co) x 32(K), 256 threads, 4x4 microtile.
// ============================================================
template <int CIN>
__global__ __launch_bounds__(256) void conv_gemm_relu(
    const float* __restrict__ X,     // [B, T, CIN]
    const float* __restrict__ Wp,    // [3*CIN, 512]
    const float* __restrict__ bias,  // [512]
    float* __restrict__ Y)           // [B, T, 512]
{
    __shared__ float As[32][68];   // As[kk][t]  (pitch 68 -> float4-aligned rows)
    __shared__ float Bs[32][64];   // Bs[kk][co]

    int b  = blockIdx.z;
    int t0 = blockIdx.x * 64;
    int n0 = blockIdx.y * 64;
    int tid = threadIdx.x;
    int tx = tid & 15, ty = tid >> 4;

    float acc[4][4] = {};

    for (int kb = 0; kb < 3 * CIN; kb += 32) {
        int ktap = kb / CIN;            // conv tap 0..2 (tiles never straddle taps)
        int cb   = kb - ktap * CIN;     // ci base
        int dt   = ktap - 1;            // time offset

        // --- load X tile (64 t x 32 ci), transpose into As[ci][t] ---
        #pragma unroll
        for (int j2 = 0; j2 < 2; j2++) {
            int j  = tid + j2 * 256;            // float4 index, 0..511
            int tt = j >> 3;                    // 0..63
            int ci = (j & 7) << 2;              // 0..28
            int tg = t0 + tt + dt;
            float4 xv = make_float4(0.f, 0.f, 0.f, 0.f);
            if (tg >= 0 && tg < Tv)
                xv = *(const float4*)(X + ((size_t)b * Tv + tg) * CIN + cb + ci);
            As[ci + 0][tt] = xv.x; As[ci + 1][tt] = xv.y;
            As[ci + 2][tt] = xv.z; As[ci + 3][tt] = xv.w;
        }
        // --- load W tile (32 kk x 64 co), row-major ---
        #pragma unroll
        for (int j2 = 0; j2 < 2; j2++) {
            int j  = tid + j2 * 256;
            int kk = j >> 4;
            int n  = (j & 15) << 2;
            *(float4*)&Bs[kk][n] = *(const float4*)(Wp + (size_t)(kb + kk) * Dv + n0 + n);
        }
        __syncthreads();

        #pragma unroll
        for (int kk = 0; kk < 32; kk++) {
            float4 a  = *(const float4*)&As[kk][ty << 2];
            float4 w4 = *(const float4*)&Bs[kk][tx << 2];
            float av[4] = {a.x, a.y, a.z, a.w};
            float wv[4] = {w4.x, w4.y, w4.z, w4.w};
            #pragma unroll
            for (int i = 0; i < 4; i++)
                #pragma unroll
                for (int jj = 0; jj < 4; jj++)
                    acc[i][jj] += av[i] * wv[jj];
        }
        __syncthreads();
    }

    #pragma unroll
    for (int i = 0; i < 4; i++) {
        int t = t0 + (ty << 2) + i;
        float4 bv = *(const float4*)(bias + n0 + (tx << 2));
        float r0 = acc[i][0] + bv.x, r1 = acc[i][1] + bv.y;
        float r2 = acc[i][2] + bv.z, r3 = acc[i][3] + bv.w;
        float4 o4 = make_float4(fmaxf(r0, 0.f), fmaxf(r1, 0.f),
                                fmaxf(r2, 0.f), fmaxf(r3, 0.f));
        *(float4*)(Y + ((size_t)b * Tv + t) * Dv + n0 + (tx << 2)) = o4;
    }
}

// ============================================================
// Time-wise flash attention. One thread = one query row.
// Writes softmax(QK^T/8) V into VAL[b,t, h*64+d] (first 512 cols).
// ============================================================
__global__ __launch_bounds__(128) void attn_time(
    const float* __restrict__ Q, const float* __restrict__ K,
    const float* __restrict__ V, float* __restrict__ VAL)
{
    __shared__ float Ks[32][64];
    __shared__ float Vs[32][64];

    int b = blockIdx.z, h = blockIdx.y;
    int trow = blockIdx.x * 128 + threadIdx.x;

    const float* qp = Q + ((size_t)b * Tv + trow) * Dv + h * HDv;
    float q[64], o[64];
    #pragma unroll
    for (int d = 0; d < 64; d += 4) *(float4*)&q[d] = *(const float4*)(qp + d);
    #pragma unroll
    for (int d = 0; d < 64; d++) o[d] = 0.f;
    float m = -1e30f, l = 0.f;

    for (int kt = 0; kt < Tv; kt += 32) {
        __syncthreads();
        #pragma unroll
        for (int j2 = 0; j2 < 4; j2++) {
            int j = threadIdx.x + j2 * 128;
            int r = j >> 4, c = (j & 15) << 2;
            size_t base = ((size_t)b * Tv + kt + r) * Dv + h * HDv + c;
            *(float4*)&Ks[r][c] = *(const float4*)(K + base);
            *(float4*)&Vs[r][c] = *(const float4*)(V + base);
        }
        __syncthreads();

        float s[32];
        #pragma unroll
        for (int j = 0; j < 32; j++) {
            float a0 = 0.f, a1 = 0.f, a2 = 0.f, a3 = 0.f;
            #pragma unroll
            for (int d = 0; d < 64; d += 4) {
                float4 kv = *(const float4*)&Ks[j][d];
                a0 += q[d] * kv.x;  a1 += q[d + 1] * kv.y;
                a2 += q[d + 2] * kv.z;  a3 += q[d + 3] * kv.w;
            }
            s[j] = (a0 + a1 + a2 + a3) * 0.125f;   // 1/sqrt(64)
        }
        float tm = m;
        #pragma unroll
        for (int j = 0; j < 32; j++) tm = fmaxf(tm, s[j]);
        float alpha = __expf(m - tm);
        m = tm;
        l *= alpha;
        #pragma unroll
        for (int d = 0; d < 64; d++) o[d] *= alpha;
        #pragma unroll
        for (int j = 0; j < 32; j++) {
            float p = __expf(s[j] - m);
            l += p;
            #pragma unroll
            for (int d = 0; d < 64; d += 4) {
                float4 vv = *(const float4*)&Vs[j][d];
                o[d]     += p * vv.x;  o[d + 1] += p * vv.y;
                o[d + 2] += p * vv.z;  o[d + 3] += p * vv.w;
            }
        }
    }
    float inv = 1.f / l;
    float* op = VAL + ((size_t)b * Tv + trow) * D2v + h * HDv;
    #pragma unroll
    for (int d = 0; d < 64; d += 4) {
        float4 w4 = make_float4(o[d] * inv, o[d + 1] * inv, o[d + 2] * inv, o[d + 3] * inv);
        *(float4*)(op + d) = w4;
    }
}

// ============================================================
// Channel-wise attention. One block per (b,h).
// S[c,d] = sum_t q[t,c] k[t,d] / 32 ; softmax rows ;
// O[c,t2] = sum_d A[c,d] v[t2,d] ; scattered write replicating the torch
// reshape: t_out = 16*c + t2/64, col = 512 + 8*(t2%64) + h.
// ============================================================
__global__ __launch_bounds__(256) void attn_chan(
    const float* __restrict__ Q, const float* __restrict__ K,
    const float* __restrict__ V, float* __restrict__ VAL)
{
    __shared__ float S[64][65];
    __shared__ float buf[64 * 68];   // phase1: Qs[32*64] + Ks[32*64]; phase3: Vst[64][68]

    int h = blockIdx.x, b = blockIdx.y;
    int tid = threadIdx.x;
    int tx = tid & 15, ty = tid >> 4;

    float* Qs = buf;
    float* Ks = buf + 32 * 64;

    float acc[4][4] = {};
    for (int t0 = 0; t0 < Tv; t0 += 32) {
        __syncthreads();
        #pragma unroll
        for (int j2 = 0; j2 < 2; j2++) {
            int j = tid + j2 * 256;
            int r = j >> 4;
            int c = (j & 15) << 2;
            size_t base = ((size_t)b * Tv + t0 + r) * Dv + h * HDv + c;
            *(float4*)&Qs[r * 64 + c] = *(const float4*)(Q + base);
            *(float4*)&Ks[r * 64 + c] = *(const float4*)(K + base);
        }
        __syncthreads();
        #pragma unroll
        for (int r = 0; r < 32; r++) {
            float4 a  = *(const float4*)&Qs[r * 64 + (ty << 2)];
            float4 w4 = *(const float4*)&Ks[r * 64 + (tx << 2)];
            float av[4] = {a.x, a.y, a.z, a.w};
            float wv[4] = {w4.x, w4.y, w4.z, w4.w};
            #pragma unroll
            for (int i = 0; i < 4; i++)
                #pragma unroll
                for (int jj = 0; jj < 4; jj++)
                    acc[i][jj] += av[i] * wv[jj];
        }
    }
    __syncthreads();
    #pragma unroll
    for (int i = 0; i < 4; i++)
        #pragma unroll
        for (int jj = 0; jj < 4; jj++)
            S[(ty << 2) + i][(tx << 2) + jj] = acc[i][jj] * 0.03125f;  // 1/sqrt(1024)
    __syncthreads();

    // row softmax (64 rows; threads 0..63)
    if (tid < 64) {
        float mx = -1e30f;
        #pragma unroll 8
        for (int d = 0; d < 64; d++) mx = fmaxf(mx, S[tid][d]);
        float sum = 0.f;
        #pragma unroll 8
        for (int d = 0; d < 64; d++) { float e = __expf(S[tid][d] - mx); S[tid][d] = e; sum += e; }
        float inv = 1.f / sum;
        #pragma unroll 8
        for (int d = 0; d < 64; d++) S[tid][d] *= inv;
    }
    __syncthreads();

    // O = A @ V^T over t2 tiles of 64
    float* Vst = buf;    // Vst[d][t2local], pitch 68
    for (int t20 = 0; t20 < Tv; t20 += 64) {
        __syncthreads();
        #pragma unroll
        for (int j2 = 0; j2 < 4; j2++) {
            int j = tid + j2 * 256;
            int r = j >> 4;            // t2 local 0..63
            int c = (j & 15) << 2;     // d
            float4 vv = *(const float4*)(V + ((size_t)b * Tv + t20 + r) * Dv + h * HDv + c);
            Vst[(c + 0) * 68 + r] = vv.x; Vst[(c + 1) * 68 + r] = vv.y;
            Vst[(c + 2) * 68 + r] = vv.z; Vst[(c + 3) * 68 + r] = vv.w;
        }
        __syncthreads();
        float o[4][4] = {};
        #pragma unroll
        for (int d = 0; d < 64; d++) {
            float a0 = S[(ty << 2) + 0][d];
            float a1 = S[(ty << 2) + 1][d];
            float a2 = S[(ty << 2) + 2][d];
            float a3 = S[(ty << 2) + 3][d];
            float4 vv = *(const float4*)&Vst[d * 68 + (tx << 2)];
            o[0][0] += a0 * vv.x; o[0][1] += a0 * vv.y; o[0][2] += a0 * vv.z; o[0][3] += a0 * vv.w;
            o[1][0] += a1 * vv.x; o[1][1] += a1 * vv.y; o[1][2] += a1 * vv.z; o[1][3] += a1 * vv.w;
            o[2][0] += a2 * vv.x; o[2][1] += a2 * vv.y; o[2][2] += a2 * vv.z; o[2][3] += a2 * vv.w;
            o[3][0] += a3 * vv.x; o[3][1] += a3 * vv.y; o[3][2] += a3 * vv.z; o[3][3] += a3 * vv.w;
        }
        #pragma unroll
        for (int i = 0; i < 4; i++) {
            int c = (ty << 2) + i;
            #pragma unroll
            for (int jj = 0; jj < 4; jj++) {
                int t2 = t20 + (tx << 2) + jj;
                int t_out = c * 16 + (t2 >> 6);
                int col = ((t2 & 63) << 3) + h;
                VAL[((size_t)b * Tv + t_out) * D2v + Dv + col] = o[i][jj];
            }
        }
    }
}

// ============================================================
// launch
// ============================================================
extern "C" void kernel_launch(void* const* d_in, const int* in_sizes, int n_in,
                              void* d_out, int out_size) {
    const float* x   = (const float*)d_in[0];
    const float* w11 = (const float*)d_in[1];
    const float* b11 = (const float*)d_in[2];
    const float* w12 = (const float*)d_in[3];
    const float* b12 = (const float*)d_in[4];
    const float* w13 = (const float*)d_in[5];
    const float* b13 = (const float*)d_in[6];
    const float* w2  = (const float*)d_in[7];
    const float* b2  = (const float*)d_in[8];
    float* out = (float*)d_out;

    float *q, *k, *v, *val, *wq, *wk, *wv, *w2p;
    cudaGetSymbolAddress((void**)&q,   g_q);
    cudaGetSymbolAddress((void**)&k,   g_k);
    cudaGetSymbolAddress((void**)&v,   g_v);
    cudaGetSymbolAddress((void**)&val, g_val);
    cudaGetSymbolAddress((void**)&wq,  g_wq);
    cudaGetSymbolAddress((void**)&wk,  g_wk);
    cudaGetSymbolAddress((void**)&wv,  g_wv);
    cudaGetSymbolAddress((void**)&w2p, g_w2);

    int tot1 = 3 * Dv * Dv;
    repack_w<<<(tot1 + 255) / 256, 256>>>(w11, wq, Dv);
    repack_w<<<(tot1 + 255) / 256, 256>>>(w12, wk, Dv);
    repack_w<<<(tot1 + 255) / 256, 256>>>(w13, wv, Dv);
    int tot2 = 3 * D2v * Dv;
    repack_w<<<(tot2 + 255) / 256, 256>>>(w2, w2p, D2v);

    dim3 gconv(Tv / 64, Dv / 64, Bv);
    conv_gemm_relu<Dv><<<gconv, 256>>>(x, wq, b11, q);
    conv_gemm_relu<Dv><<<gconv, 256>>>(x, wk, b12, k);
    conv_gemm_relu<Dv><<<gconv, 256>>>(x, wv, b13, v);

    attn_time<<<dim3(Tv / 128, Hv, Bv), 128>>>(q, k, v, val);
    attn_chan<<<dim3(Hv, Bv), 256>>>(q, k, v, val);

    conv_gemm_relu<D2v><<<gconv, 256>>>(val, w2p, b2, out);
}

// round 3
// speedup vs baseline: 1.6589x; 1.6589x over previous
#include <cuda_runtime.h>
#include <cuda_bf16.h>
#include <cstdint>

// ---- problem dims ----
#define Bv   8
#define Tv   1024
#define Dv   512
#define Hv   8
#define HDv  64
#define D2v  1024

// ---- scratch ----
__device__ float g_q[Bv * Tv * Dv];
__device__ float g_k[Bv * Tv * Dv];
__device__ float g_v[Bv * Tv * Dv];
__device__ __nv_bfloat16 g_xh[Bv * Tv * Dv];
__device__ __nv_bfloat16 g_xl[Bv * Tv * Dv];
__device__ __nv_bfloat16 g_valh[Bv * Tv * D2v];
__device__ __nv_bfloat16 g_vall[Bv * Tv * D2v];
__device__ __nv_bfloat16 g_wqh[3 * Dv * Dv];
__device__ __nv_bfloat16 g_wql[3 * Dv * Dv];
__device__ __nv_bfloat16 g_wkh[3 * Dv * Dv];
__device__ __nv_bfloat16 g_wkl[3 * Dv * Dv];
__device__ __nv_bfloat16 g_wvh[3 * Dv * Dv];
__device__ __nv_bfloat16 g_wvl[3 * Dv * Dv];
__device__ __nv_bfloat16 g_w2h[3 * D2v * Dv];
__device__ __nv_bfloat16 g_w2l[3 * D2v * Dv];

// ============================================================
// warp-level MMA helpers (sm_80-baseline features only)
// ============================================================
__device__ __forceinline__ uint32_t smem_u32(const void* p) {
    uint32_t a;
    asm("{ .reg .u64 t; cvta.to.shared.u64 t, %1; cvt.u32.u64 %0, t; }"
        : "=r"(a) : "l"(p));
    return a;
}

__device__ __forceinline__ void ldsm4(uint32_t* r, uint32_t addr) {
    asm volatile("ldmatrix.sync.aligned.m8n8.x4.shared.b16 {%0,%1,%2,%3}, [%4];"
                 : "=r"(r[0]), "=r"(r[1]), "=r"(r[2]), "=r"(r[3]) : "r"(addr));
}

__device__ __forceinline__ void mma16816(float* c, const uint32_t* a, const uint32_t* b) {
    asm volatile(
        "mma.sync.aligned.m16n8k16.row.col.f32.bf16.bf16.f32 "
        "{%0,%1,%2,%3}, {%4,%5,%6,%7}, {%8,%9}, {%0,%1,%2,%3};"
        : "+f"(c[0]), "+f"(c[1]), "+f"(c[2]), "+f"(c[3])
        : "r"(a[0]), "r"(a[1]), "r"(a[2]), "r"(a[3]), "r"(b[0]), "r"(b[1]));
}

// 128B-row swizzle: addr = row*128 + (col ^ ((row&7)<<4))
__device__ __forceinline__ uint32_t sm_addr(uint32_t base, int row, int col) {
    return base + (uint32_t)(row * 128 + (col ^ ((row & 7) << 4)));
}

// ============================================================
// split fp32 -> (bf16 hi, bf16 lo)
// ============================================================
__global__ void split_f32(const float* __restrict__ x, __nv_bfloat16* __restrict__ hi,
                          __nv_bfloat16* __restrict__ lo, int n) {
    int i = blockIdx.x * 256 + threadIdx.x;
    if (i >= n) return;
    float v = x[i];
    __nv_bfloat16 h = __float2bfloat16(v);
    hi[i] = h;
    lo[i] = __float2bfloat16(v - __bfloat162float(h));
}

// ============================================================
// repack + split weights: w[co,ci,tap] -> wp[co][tap*cin+ci]  (bf16 hi/lo)
// ============================================================
__global__ void repack_wsplit(const float* __restrict__ w, __nv_bfloat16* __restrict__ hi,
                              __nv_bfloat16* __restrict__ lo, int cin) {
    int idx = blockIdx.x * 256 + threadIdx.x;
    int total = 3 * cin * Dv;
    if (idx >= total) return;
    int kk = idx % (3 * cin);
    int co = idx / (3 * cin);
    int tap = kk / cin;
    int ci  = kk - tap * cin;
    float v = w[((size_t)co * cin + ci) * 3 + tap];
    __nv_bfloat16 h = __float2bfloat16(v);
    hi[idx] = h;
    lo[idx] = __float2bfloat16(v - __bfloat162float(h));
}

// ============================================================
// conv1d(k=3,'same') + bias + ReLU via mma.sync bf16x3.
// CTA tile 128(t) x 128(co); K in 64-element bf16 chunks, double-buffered.
// 8 warps: wm = wid&3 (32 rows each), wn = wid>>2 (64 cols each).
// acc = Ah*Bh + Al*Bh + Ah*Bl  (fp32 accum; drops only lo*lo ~ 2^-16)
// ============================================================
#define STAGE_BYTES 65536     // Ah 16K | Al 16K | Bh 16K | Bl 16K
#define SMEM_TOTAL  (2 * STAGE_BYTES)

template <int CIN, bool RELU>
__global__ __launch_bounds__(256, 1)
void conv_hmma(const __nv_bfloat16* __restrict__ Xh, const __nv_bfloat16* __restrict__ Xl,
               const __nv_bfloat16* __restrict__ Wh, const __nv_bfloat16* __restrict__ Wl,
               const float* __restrict__ bias, float* __restrict__ Y) {
    extern __shared__ __align__(1024) char sm[];
    const uint32_t smb = smem_u32(sm);
    const int tid = threadIdx.x;
    const int b  = blockIdx.z;
    const int t0 = blockIdx.x * 128;
    const int n0 = blockIdx.y * 128;
    constexpr int KTOT = 3 * CIN;
    constexpr int C = KTOT / 64;

    const int lane = tid & 31, wid = tid >> 5;
    const int wm = wid & 3, wn = wid >> 2;
    const int rr = lane & 7, tt = lane >> 3;
    // per-lane ldmatrix row/col bases
    const int arow = wm * 32 + (tt & 1) * 8 + rr;
    const int acol = (tt >> 1) * 16;
    const int brow = wn * 64 + (tt >> 1) * 8 + rr;
    const int bcol = (tt & 1) * 16;

    float acc[2][8][4] = {};

    auto stage = [&](int c, int st) {
        const int kb  = c * 64;
        const int tap = kb / CIN;
        const int cb  = kb - tap * CIN;
        const int dt  = tap - 1;
        char* base = sm + st * STAGE_BYTES;
        const uint4 z = make_uint4(0, 0, 0, 0);
        #pragma unroll
        for (int j = 0; j < 4; j++) {
            int u  = tid + j * 256;          // 0..1023
            int r  = u >> 3;                 // row 0..127
            int cu = u & 7;                  // 16B unit in 128B row
            uint32_t sw = (uint32_t)(r * 128 + ((cu * 16) ^ ((r & 7) << 4)));
            // A (hi/lo), halo-predicated
            int tg = t0 + r + dt;
            uint4 vh = z, vl = z;
            if (tg >= 0 && tg < Tv) {
                size_t off = ((size_t)(b * Tv + tg) * CIN + cb + cu * 8) >> 3;
                vh = ((const uint4*)Xh)[off];
                vl = ((const uint4*)Xl)[off];
            }
            *(uint4*)(base + sw)         = vh;
            *(uint4*)(base + 16384 + sw) = vl;
            // B (hi/lo)
            size_t woff = ((size_t)(n0 + r) * KTOT + kb + cu * 8) >> 3;
            *(uint4*)(base + 32768 + sw) = ((const uint4*)Wh)[woff];
            *(uint4*)(base + 49152 + sw) = ((const uint4*)Wl)[woff];
        }
    };

    auto compute = [&](int st) {
        const uint32_t ah_b = smb + st * STAGE_BYTES;
        const uint32_t al_b = ah_b + 16384;
        const uint32_t bh_b = ah_b + 32768;
        const uint32_t bl_b = ah_b + 49152;
        #pragma unroll
        for (int ks = 0; ks < 4; ks++) {
            uint32_t Ah[2][4], Al[2][4], Bh[8][2], Bl[8][2];
            #pragma unroll
            for (int mi = 0; mi < 2; mi++) {
                ldsm4(Ah[mi], sm_addr(ah_b, arow + mi * 16, acol + ks * 32));
                ldsm4(Al[mi], sm_addr(al_b, arow + mi * 16, acol + ks * 32));
            }
            #pragma unroll
            for (int jp = 0; jp < 4; jp++) {
                uint32_t r4[4];
                ldsm4(r4, sm_addr(bh_b, brow + jp * 16, bcol + ks * 32));
                Bh[2 * jp][0] = r4[0]; Bh[2 * jp][1] = r4[1];
                Bh[2 * jp + 1][0] = r4[2]; Bh[2 * jp + 1][1] = r4[3];
                ldsm4(r4, sm_addr(bl_b, brow + jp * 16, bcol + ks * 32));
                Bl[2 * jp][0] = r4[0]; Bl[2 * jp][1] = r4[1];
                Bl[2 * jp + 1][0] = r4[2]; Bl[2 * jp + 1][1] = r4[3];
            }
            #pragma unroll
            for (int mi = 0; mi < 2; mi++)
                #pragma unroll
                for (int nj = 0; nj < 8; nj++) {
                    mma16816(acc[mi][nj], Ah[mi], Bh[nj]);
                    mma16816(acc[mi][nj], Al[mi], Bh[nj]);
                    mma16816(acc[mi][nj], Ah[mi], Bl[nj]);
                }
        }
    };

    stage(0, 0);
    __syncthreads();
    for (int c = 0; c < C; c++) {
        int st = c & 1;
        if (c + 1 < C) stage(c + 1, st ^ 1);
        compute(st);
        __syncthreads();
    }

    // epilogue: C frag thread map: rows lane>>2 (+8), cols 2*(lane&3)
    const int r0 = lane >> 2;
    const int c0 = (lane & 3) * 2;
    #pragma unroll
    for (int mi = 0; mi < 2; mi++) {
        int mg = t0 + wm * 32 + mi * 16 + r0;
        float* y0 = Y + ((size_t)(b * Tv + mg)) * Dv;
        float* y1 = Y + ((size_t)(b * Tv + mg + 8)) * Dv;
        #pragma unroll
        for (int nj = 0; nj < 8; nj++) {
            int ng = n0 + wn * 64 + nj * 8 + c0;
            float2 bv = *(const float2*)(bias + ng);
            float v0 = acc[mi][nj][0] + bv.x;
            float v1 = acc[mi][nj][1] + bv.y;
            float v2 = acc[mi][nj][2] + bv.x;
            float v3 = acc[mi][nj][3] + bv.y;
            if (RELU) {
                v0 = fmaxf(v0, 0.f); v1 = fmaxf(v1, 0.f);
                v2 = fmaxf(v2, 0.f); v3 = fmaxf(v3, 0.f);
            }
            *(float2*)(y0 + ng) = make_float2(v0, v1);
            *(float2*)(y1 + ng) = make_float2(v2, v3);
        }
    }
}

// ============================================================
// Time-wise flash attention (fp32). Writes bf16 hi/lo into VAL cols [0,512).
// ============================================================
__global__ __launch_bounds__(128) void attn_time(
    const float* __restrict__ Q, const float* __restrict__ K,
    const float* __restrict__ V, __nv_bfloat16* __restrict__ VALh,
    __nv_bfloat16* __restrict__ VALl)
{
    __shared__ float Ks[32][64];
    __shared__ float Vs[32][64];

    int b = blockIdx.z, h = blockIdx.y;
    int trow = blockIdx.x * 128 + threadIdx.x;

    const float* qp = Q + ((size_t)b * Tv + trow) * Dv + h * HDv;
    float q[64], o[64];
    #pragma unroll
    for (int d = 0; d < 64; d += 4) *(float4*)&q[d] = *(const float4*)(qp + d);
    #pragma unroll
    for (int d = 0; d < 64; d++) o[d] = 0.f;
    float m = -1e30f, l = 0.f;

    for (int kt = 0; kt < Tv; kt += 32) {
        __syncthreads();
        #pragma unroll
        for (int j2 = 0; j2 < 4; j2++) {
            int j = threadIdx.x + j2 * 128;
            int r = j >> 4, c = (j & 15) << 2;
            size_t base = ((size_t)b * Tv + kt + r) * Dv + h * HDv + c;
            *(float4*)&Ks[r][c] = *(const float4*)(K + base);
            *(float4*)&Vs[r][c] = *(const float4*)(V + base);
        }
        __syncthreads();

        float s[32];
        #pragma unroll
        for (int j = 0; j < 32; j++) {
            float a0 = 0.f, a1 = 0.f, a2 = 0.f, a3 = 0.f;
            #pragma unroll
            for (int d = 0; d < 64; d += 4) {
                float4 kv = *(const float4*)&Ks[j][d];
                a0 += q[d] * kv.x;  a1 += q[d + 1] * kv.y;
                a2 += q[d + 2] * kv.z;  a3 += q[d + 3] * kv.w;
            }
            s[j] = (a0 + a1 + a2 + a3) * 0.125f;
        }
        float tm = m;
        #pragma unroll
        for (int j = 0; j < 32; j++) tm = fmaxf(tm, s[j]);
        float alpha = __expf(m - tm);
        m = tm;
        l *= alpha;
        #pragma unroll
        for (int d = 0; d < 64; d++) o[d] *= alpha;
        #pragma unroll
        for (int j = 0; j < 32; j++) {
            float p = __expf(s[j] - m);
            l += p;
            #pragma unroll
            for (int d = 0; d < 64; d += 4) {
                float4 vv = *(const float4*)&Vs[j][d];
                o[d]     += p * vv.x;  o[d + 1] += p * vv.y;
                o[d + 2] += p * vv.z;  o[d + 3] += p * vv.w;
            }
        }
    }
    float inv = 1.f / l;
    size_t ob = ((size_t)b * Tv + trow) * D2v + h * HDv;
    #pragma unroll
    for (int d = 0; d < 64; d += 2) {
        float v0 = o[d] * inv, v1 = o[d + 1] * inv;
        __nv_bfloat16 h0 = __float2bfloat16(v0), h1 = __float2bfloat16(v1);
        __nv_bfloat16 l0 = __float2bfloat16(v0 - __bfloat162float(h0));
        __nv_bfloat16 l1 = __float2bfloat16(v1 - __bfloat162float(h1));
        *(__nv_bfloat162*)(VALh + ob + d) = __nv_bfloat162(h0, h1);
        *(__nv_bfloat162*)(VALl + ob + d) = __nv_bfloat162(l0, l1);
    }
}

// ============================================================
// Channel-wise attention (fp32). Scattered bf16 hi/lo writes, cols [512,1024).
// ============================================================
__global__ __launch_bounds__(256) void attn_chan(
    const float* __restrict__ Q, const float* __restrict__ K,
    const float* __restrict__ V, __nv_bfloat16* __restrict__ VALh,
    __nv_bfloat16* __restrict__ VALl)
{
    __shared__ float S[64][65];
    __shared__ float buf[64 * 68];

    int h = blockIdx.x, b = blockIdx.y;
    int tid = threadIdx.x;
    int tx = tid & 15, ty = tid >> 4;

    float* Qs = buf;
    float* Ks = buf + 32 * 64;

    float acc[4][4] = {};
    for (int t0 = 0; t0 < Tv; t0 += 32) {
        __syncthreads();
        #pragma unroll
        for (int j2 = 0; j2 < 2; j2++) {
            int j = tid + j2 * 256;
            int r = j >> 4;
            int c = (j & 15) << 2;
            size_t base = ((size_t)b * Tv + t0 + r) * Dv + h * HDv + c;
            *(float4*)&Qs[r * 64 + c] = *(const float4*)(Q + base);
            *(float4*)&Ks[r * 64 + c] = *(const float4*)(K + base);
        }
        __syncthreads();
        #pragma unroll
        for (int r = 0; r < 32; r++) {
            float4 a  = *(const float4*)&Qs[r * 64 + (ty << 2)];
            float4 w4 = *(const float4*)&Ks[r * 64 + (tx << 2)];
            float av[4] = {a.x, a.y, a.z, a.w};
            float wv[4] = {w4.x, w4.y, w4.z, w4.w};
            #pragma unroll
            for (int i = 0; i < 4; i++)
                #pragma unroll
                for (int jj = 0; jj < 4; jj++)
                    acc[i][jj] += av[i] * wv[jj];
        }
    }
    __syncthreads();
    #pragma unroll
    for (int i = 0; i < 4; i++)
        #pragma unroll
        for (int jj = 0; jj < 4; jj++)
            S[(ty << 2) + i][(tx << 2) + jj] = acc[i][jj] * 0.03125f;
    __syncthreads();

    if (tid < 64) {
        float mx = -1e30f;
        #pragma unroll 8
        for (int d = 0; d < 64; d++) mx = fmaxf(mx, S[tid][d]);
        float sum = 0.f;
        #pragma unroll 8
        for (int d = 0; d < 64; d++) { float e = __expf(S[tid][d] - mx); S[tid][d] = e; sum += e; }
        float inv = 1.f / sum;
        #pragma unroll 8
        for (int d = 0; d < 64; d++) S[tid][d] *= inv;
    }
    __syncthreads();

    float* Vst = buf;
    for (int t20 = 0; t20 < Tv; t20 += 64) {
        __syncthreads();
        #pragma unroll
        for (int j2 = 0; j2 < 4; j2++) {
            int j = tid + j2 * 256;
            int r = j >> 4;
            int c = (j & 15) << 2;
            float4 vv = *(const float4*)(V + ((size_t)b * Tv + t20 + r) * Dv + h * HDv + c);
            Vst[(c + 0) * 68 + r] = vv.x; Vst[(c + 1) * 68 + r] = vv.y;
            Vst[(c + 2) * 68 + r] = vv.z; Vst[(c + 3) * 68 + r] = vv.w;
        }
        __syncthreads();
        float o[4][4] = {};
        #pragma unroll
        for (int d = 0; d < 64; d++) {
            float a0 = S[(ty << 2) + 0][d];
            float a1 = S[(ty << 2) + 1][d];
            float a2 = S[(ty << 2) + 2][d];
            float a3 = S[(ty << 2) + 3][d];
            float4 vv = *(const float4*)&Vst[d * 68 + (tx << 2)];
            o[0][0] += a0 * vv.x; o[0][1] += a0 * vv.y; o[0][2] += a0 * vv.z; o[0][3] += a0 * vv.w;
            o[1][0] += a1 * vv.x; o[1][1] += a1 * vv.y; o[1][2] += a1 * vv.z; o[1][3] += a1 * vv.w;
            o[2][0] += a2 * vv.x; o[2][1] += a2 * vv.y; o[2][2] += a2 * vv.z; o[2][3] += a2 * vv.w;
            o[3][0] += a3 * vv.x; o[3][1] += a3 * vv.y; o[3][2] += a3 * vv.z; o[3][3] += a3 * vv.w;
        }
        #pragma unroll
        for (int i = 0; i < 4; i++) {
            int c = (ty << 2) + i;
            #pragma unroll
            for (int jj = 0; jj < 4; jj++) {
                int t2 = t20 + (tx << 2) + jj;
                int t_out = c * 16 + (t2 >> 6);
                int col = ((t2 & 63) << 3) + h;
                size_t idx = ((size_t)b * Tv + t_out) * D2v + Dv + col;
                float v = o[i][jj];
                __nv_bfloat16 hh = __float2bfloat16(v);
                VALh[idx] = hh;
                VALl[idx] = __float2bfloat16(v - __bfloat162float(hh));
            }
        }
    }
}

// ============================================================
// launch
// ============================================================
extern "C" void kernel_launch(void* const* d_in, const int* in_sizes, int n_in,
                              void* d_out, int out_size) {
    const float* x   = (const float*)d_in[0];
    const float* w11 = (const float*)d_in[1];
    const float* b11 = (const float*)d_in[2];
    const float* w12 = (const float*)d_in[3];
    const float* b12 = (const float*)d_in[4];
    const float* w13 = (const float*)d_in[5];
    const float* b13 = (const float*)d_in[6];
    const float* w2  = (const float*)d_in[7];
    const float* b2  = (const float*)d_in[8];
    float* out = (float*)d_out;

    float *q, *k, *v;
    __nv_bfloat16 *xh, *xl, *valh, *vall;
    __nv_bfloat16 *wqh, *wql, *wkh, *wkl, *wvh, *wvl, *w2h, *w2l;
    cudaGetSymbolAddress((void**)&q,    g_q);
    cudaGetSymbolAddress((void**)&k,    g_k);
    cudaGetSymbolAddress((void**)&v,    g_v);
    cudaGetSymbolAddress((void**)&xh,   g_xh);
    cudaGetSymbolAddress((void**)&xl,   g_xl);
    cudaGetSymbolAddress((void**)&valh, g_valh);
    cudaGetSymbolAddress((void**)&vall, g_vall);
    cudaGetSymbolAddress((void**)&wqh,  g_wqh);
    cudaGetSymbolAddress((void**)&wql,  g_wql);
    cudaGetSymbolAddress((void**)&wkh,  g_wkh);
    cudaGetSymbolAddress((void**)&wkl,  g_wkl);
    cudaGetSymbolAddress((void**)&wvh,  g_wvh);
    cudaGetSymbolAddress((void**)&wvl,  g_wvl);
    cudaGetSymbolAddress((void**)&w2h,  g_w2h);
    cudaGetSymbolAddress((void**)&w2l,  g_w2l);

    cudaFuncSetAttribute(conv_hmma<Dv, true>,
                         cudaFuncAttributeMaxDynamicSharedMemorySize, SMEM_TOTAL);
    cudaFuncSetAttribute(conv_hmma<D2v, true>,
                         cudaFuncAttributeMaxDynamicSharedMemorySize, SMEM_TOTAL);

    int nx = Bv * Tv * Dv;
    split_f32<<<(nx + 255) / 256, 256>>>(x, xh, xl, nx);
    int tot1 = 3 * Dv * Dv;
    repack_wsplit<<<(tot1 + 255) / 256, 256>>>(w11, wqh, wql, Dv);
    repack_wsplit<<<(tot1 + 255) / 256, 256>>>(w12, wkh, wkl, Dv);
    repack_wsplit<<<(tot1 + 255) / 256, 256>>>(w13, wvh, wvl, Dv);
    int tot2 = 3 * D2v * Dv;
    repack_wsplit<<<(tot2 + 255) / 256, 256>>>(w2, w2h, w2l, D2v);

    dim3 gconv(Tv / 128, Dv / 128, Bv);
    conv_hmma<Dv, true><<<gconv, 256, SMEM_TOTAL>>>(xh, xl, wqh, wql, b11, q);
    conv_hmma<Dv, true><<<gconv, 256, SMEM_TOTAL>>>(xh, xl, wkh, wkl, b12, k);
    conv_hmma<Dv, true><<<gconv, 256, SMEM_TOTAL>>>(xh, xl, wvh, wvl, b13, v);

    attn_time<<<dim3(Tv / 128, Hv, Bv), 128>>>(q, k, v, valh, vall);
    attn_chan<<<dim3(Hv, Bv), 256>>>(q, k, v, valh, vall);

    conv_hmma<D2v, true><<<gconv, 256, SMEM_TOTAL>>>(valh, vall, w2h, w2l, b2, out);
}

// round 4
// speedup vs baseline: 2.7365x; 1.6496x over previous
#include <cuda_runtime.h>
#include <cuda_bf16.h>
#include <cstdint>

// ---- problem dims ----
#define Bv   8
#define Tv   1024
#define Dv   512
#define Hv   8
#define HDv  64
#define D2v  1024

// ---- scratch ----
__device__ float g_q[Bv * Tv * Dv];
__device__ float g_k[Bv * Tv * Dv];
__device__ float g_v[Bv * Tv * Dv];
__device__ __nv_bfloat16 g_xh[Bv * Tv * Dv];
__device__ __nv_bfloat16 g_xl[Bv * Tv * Dv];
__device__ __nv_bfloat16 g_qh[Bv * Tv * Dv];   // pre-scaled by 0.125
__device__ __nv_bfloat16 g_ql[Bv * Tv * Dv];
__device__ __nv_bfloat16 g_kh[Bv * Tv * Dv];
__device__ __nv_bfloat16 g_kl[Bv * Tv * Dv];
__device__ __nv_bfloat16 g_vh[Bv * Tv * Dv];
__device__ __nv_bfloat16 g_vl[Bv * Tv * Dv];
__device__ __nv_bfloat16 g_valh[Bv * Tv * D2v];
__device__ __nv_bfloat16 g_vall[Bv * Tv * D2v];
__device__ __nv_bfloat16 g_wqh[3 * Dv * Dv];
__device__ __nv_bfloat16 g_wql[3 * Dv * Dv];
__device__ __nv_bfloat16 g_wkh[3 * Dv * Dv];
__device__ __nv_bfloat16 g_wkl[3 * Dv * Dv];
__device__ __nv_bfloat16 g_wvh[3 * Dv * Dv];
__device__ __nv_bfloat16 g_wvl[3 * Dv * Dv];
__device__ __nv_bfloat16 g_w2h[3 * D2v * Dv];
__device__ __nv_bfloat16 g_w2l[3 * D2v * Dv];

// ============================================================
// helpers (sm_80-baseline PTX only)
// ============================================================
__device__ __forceinline__ uint32_t smem_u32(const void* p) {
    uint32_t a;
    asm("{ .reg .u64 t; cvta.to.shared.u64 t, %1; cvt.u32.u64 %0, t; }"
        : "=r"(a) : "l"(p));
    return a;
}

__device__ __forceinline__ void ldsm4(uint32_t* r, uint32_t addr) {
    asm volatile("ldmatrix.sync.aligned.m8n8.x4.shared.b16 {%0,%1,%2,%3}, [%4];"
                 : "=r"(r[0]), "=r"(r[1]), "=r"(r[2]), "=r"(r[3]) : "r"(addr));
}
__device__ __forceinline__ void ldsm4t(uint32_t* r, uint32_t addr) {
    asm volatile("ldmatrix.sync.aligned.m8n8.x4.trans.shared.b16 {%0,%1,%2,%3}, [%4];"
                 : "=r"(r[0]), "=r"(r[1]), "=r"(r[2]), "=r"(r[3]) : "r"(addr));
}

__device__ __forceinline__ void mma16816(float* c, const uint32_t* a, const uint32_t* b) {
    asm volatile(
        "mma.sync.aligned.m16n8k16.row.col.f32.bf16.bf16.f32 "
        "{%0,%1,%2,%3}, {%4,%5,%6,%7}, {%8,%9}, {%0,%1,%2,%3};"
        : "+f"(c[0]), "+f"(c[1]), "+f"(c[2]), "+f"(c[3])
        : "r"(a[0]), "r"(a[1]), "r"(a[2]), "r"(a[3]), "r"(b[0]), "r"(b[1]));
}

__device__ __forceinline__ void cp16(uint32_t dst, const void* src, uint32_t n) {
    asm volatile("cp.async.cg.shared.global [%0], [%1], 16, %2;"
                 :: "r"(dst), "l"(__cvta_generic_to_global(src)), "r"(n));
}
#define CP_COMMIT  asm volatile("cp.async.commit_group;" ::: "memory")
#define CP_WAIT(n) asm volatile("cp.async.wait_group %0;" :: "n"(n) : "memory")

// pack two fp32 -> bf16x2 (lo half = first arg)
__device__ __forceinline__ uint32_t packbf(float lo, float hi) {
    uint32_t r;
    asm("cvt.rn.bf16x2.f32 %0, %1, %2;" : "=r"(r) : "f"(hi), "f"(lo));
    return r;
}

// 128B-row swizzle
__device__ __forceinline__ uint32_t sm_addr(uint32_t base, int row, int col) {
    return base + (uint32_t)(row * 128 + (col ^ ((row & 7) << 4)));
}

// ============================================================
// transforms
// ============================================================
__global__ void split_f32(const float* __restrict__ x, __nv_bfloat16* __restrict__ hi,
                          __nv_bfloat16* __restrict__ lo, int n) {
    int i = blockIdx.x * 256 + threadIdx.x;
    if (i >= n) return;
    float v = x[i];
    __nv_bfloat16 h = __float2bfloat16(v);
    hi[i] = h;
    lo[i] = __float2bfloat16(v - __bfloat162float(h));
}

__global__ void repack_wsplit(const float* __restrict__ w, __nv_bfloat16* __restrict__ hi,
                              __nv_bfloat16* __restrict__ lo, int cin) {
    int idx = blockIdx.x * 256 + threadIdx.x;
    int total = 3 * cin * Dv;
    if (idx >= total) return;
    int kk = idx % (3 * cin);
    int co = idx / (3 * cin);
    int tap = kk / cin;
    int ci  = kk - tap * cin;
    float v = w[((size_t)co * cin + ci) * 3 + tap];
    __nv_bfloat16 h = __float2bfloat16(v);
    hi[idx] = h;
    lo[idx] = __float2bfloat16(v - __bfloat162float(h));
}

// ============================================================
// conv1d(k=3,'same') + bias + ReLU via mma.sync bf16x3, cp.async pipeline.
// ============================================================
#define STAGE_BYTES 65536     // Ah 16K | Al 16K | Bh 16K | Bl 16K
#define SMEM_TOTAL  (2 * STAGE_BYTES)

template <int CIN, bool RELU, bool WSPLIT>
__global__ __launch_bounds__(256, 1)
void conv_hmma(const __nv_bfloat16* __restrict__ Xh, const __nv_bfloat16* __restrict__ Xl,
               const __nv_bfloat16* __restrict__ Wh, const __nv_bfloat16* __restrict__ Wl,
               const float* __restrict__ bias, float* __restrict__ Y,
               __nv_bfloat16* __restrict__ Yh, __nv_bfloat16* __restrict__ Yl,
               float oscale) {
    extern __shared__ __align__(1024) char sm[];
    const uint32_t smb = smem_u32(sm);
    const int tid = threadIdx.x;
    const int b  = blockIdx.z;
    const int t0 = blockIdx.x * 128;
    const int n0 = blockIdx.y * 128;
    constexpr int KTOT = 3 * CIN;
    constexpr int C = KTOT / 64;

    const int lane = tid & 31, wid = tid >> 5;
    const int wm = wid & 3, wn = wid >> 2;
    const int rr = lane & 7, tt = lane >> 3;
    const int arow = wm * 32 + (tt & 1) * 8 + rr;
    const int acol = (tt >> 1) * 16;
    const int brow = wn * 64 + (tt >> 1) * 8 + rr;
    const int bcol = (tt & 1) * 16;

    float acc[2][8][4] = {};

    auto stage = [&](int c, int st) {
        const int kb  = c * 64;
        const int tap = kb / CIN;
        const int cb  = kb - tap * CIN;
        const int dt  = tap - 1;
        uint32_t base = smb + st * STAGE_BYTES;
        #pragma unroll
        for (int j = 0; j < 4; j++) {
            int u  = tid + j * 256;
            int r  = u >> 3;
            int cu = u & 7;
            uint32_t sw = (uint32_t)(r * 128 + ((cu * 16) ^ ((r & 7) << 4)));
            int tg = t0 + r + dt;
            uint32_t ok = (tg >= 0 && tg < Tv) ? 16u : 0u;
            int tc = min(max(tg, 0), Tv - 1);
            size_t aoff = (size_t)(b * Tv + tc) * CIN + cb + cu * 8;
            cp16(base + sw,         Xh + aoff, ok);
            cp16(base + 16384 + sw, Xl + aoff, ok);
            size_t woff = (size_t)(n0 + r) * KTOT + kb + cu * 8;
            cp16(base + 32768 + sw, Wh + woff, 16u);
            cp16(base + 49152 + sw, Wl + woff, 16u);
        }
    };

    auto compute = [&](int st) {
        const uint32_t ah_b = smb + st * STAGE_BYTES;
        const uint32_t al_b = ah_b + 16384;
        const uint32_t bh_b = ah_b + 32768;
        const uint32_t bl_b = ah_b + 49152;
        #pragma unroll
        for (int ks = 0; ks < 4; ks++) {
            uint32_t Ah[2][4], Al[2][4], Bh[8][2], Bl[8][2];
            #pragma unroll
            for (int mi = 0; mi < 2; mi++) {
                ldsm4(Ah[mi], sm_addr(ah_b, arow + mi * 16, acol + ks * 32));
                ldsm4(Al[mi], sm_addr(al_b, arow + mi * 16, acol + ks * 32));
            }
            #pragma unroll
            for (int jp = 0; jp < 4; jp++) {
                uint32_t r4[4];
                ldsm4(r4, sm_addr(bh_b, brow + jp * 16, bcol + ks * 32));
                Bh[2 * jp][0] = r4[0]; Bh[2 * jp][1] = r4[1];
                Bh[2 * jp + 1][0] = r4[2]; Bh[2 * jp + 1][1] = r4[3];
                ldsm4(r4, sm_addr(bl_b, brow + jp * 16, bcol + ks * 32));
                Bl[2 * jp][0] = r4[0]; Bl[2 * jp][1] = r4[1];
                Bl[2 * jp + 1][0] = r4[2]; Bl[2 * jp + 1][1] = r4[3];
            }
            #pragma unroll
            for (int mi = 0; mi < 2; mi++)
                #pragma unroll
                for (int nj = 0; nj < 8; nj++) {
                    mma16816(acc[mi][nj], Ah[mi], Bh[nj]);
                    mma16816(acc[mi][nj], Al[mi], Bh[nj]);
                    mma16816(acc[mi][nj], Ah[mi], Bl[nj]);
                }
        }
    };

    stage(0, 0);
    CP_COMMIT;
    for (int c = 0; c < C; c++) {
        if (c + 1 < C) { stage(c + 1, (c + 1) & 1); CP_COMMIT; CP_WAIT(1); }
        else           { CP_WAIT(0); }
        __syncthreads();
        compute(c & 1);
        __syncthreads();
    }

    const int r0 = lane >> 2;
    const int c0 = (lane & 3) * 2;
    #pragma unroll
    for (int mi = 0; mi < 2; mi++) {
        int mg = t0 + wm * 32 + mi * 16 + r0;
        float* y0 = Y + (size_t)(b * Tv + mg) * Dv;
        float* y1 = Y + (size_t)(b * Tv + mg + 8) * Dv;
        #pragma unroll
        for (int nj = 0; nj < 8; nj++) {
            int ng = n0 + wn * 64 + nj * 8 + c0;
            float2 bv = *(const float2*)(bias + ng);
            float v0 = acc[mi][nj][0] + bv.x;
            float v1 = acc[mi][nj][1] + bv.y;
            float v2 = acc[mi][nj][2] + bv.x;
            float v3 = acc[mi][nj][3] + bv.y;
            if (RELU) {
                v0 = fmaxf(v0, 0.f); v1 = fmaxf(v1, 0.f);
                v2 = fmaxf(v2, 0.f); v3 = fmaxf(v3, 0.f);
            }
            *(float2*)(y0 + ng) = make_float2(v0, v1);
            *(float2*)(y1 + ng) = make_float2(v2, v3);
            if (WSPLIT) {
                float s0 = v0 * oscale, s1 = v1 * oscale;
                float s2 = v2 * oscale, s3 = v3 * oscale;
                float h0 = __bfloat162float(__float2bfloat16(s0));
                float h1 = __bfloat162float(__float2bfloat16(s1));
                float h2 = __bfloat162float(__float2bfloat16(s2));
                float h3 = __bfloat162float(__float2bfloat16(s3));
                size_t o0 = (size_t)(b * Tv + mg) * Dv + ng;
                size_t o1 = (size_t)(b * Tv + mg + 8) * Dv + ng;
                *(uint32_t*)(Yh + o0) = packbf(h0, h1);
                *(uint32_t*)(Yl + o0) = packbf(s0 - h0, s1 - h1);
                *(uint32_t*)(Yh + o1) = packbf(h2, h3);
                *(uint32_t*)(Yl + o1) = packbf(s2 - h2, s3 - h3);
            }
        }
    }
}

// ============================================================
// Time-wise flash attention via mma.sync bf16x3.
// CTA: 256 thr (8 warps), 128 query rows; K/V chunks of 64 keys, cp.async 2-stage.
// Q pre-scaled by 1/sqrt(64)=0.125 (exact in bf16 split).
// ============================================================
#define AT_STAGE 32768   // Kh 8K | Kl 8K | Vh 8K | Vl 8K
#define AT_KV    32768   // Q (Qh 16K | Ql 16K) at 0
#define AT_SMEM  (AT_KV + 2 * AT_STAGE)   // 96KB

__global__ __launch_bounds__(256, 1)
void attn_time_hmma(const __nv_bfloat16* __restrict__ Qh, const __nv_bfloat16* __restrict__ Ql,
                    const __nv_bfloat16* __restrict__ Kh, const __nv_bfloat16* __restrict__ Kl,
                    const __nv_bfloat16* __restrict__ Vh, const __nv_bfloat16* __restrict__ Vl,
                    __nv_bfloat16* __restrict__ Oh, __nv_bfloat16* __restrict__ Ol) {
    extern __shared__ __align__(1024) char sm[];
    const uint32_t smb = smem_u32(sm);
    const int tid = threadIdx.x, lane = tid & 31, wid = tid >> 5;
    const int b = blockIdx.z, h = blockIdx.y, t0 = blockIdx.x * 128;
    const int rr = lane & 7, tt = lane >> 3;

    // --- stage Q (hi/lo) ---
    #pragma unroll
    for (int j = 0; j < 8; j++) {
        int u = tid + j * 256;          // 0..2047
        int half = u >> 10;
        int w = u & 1023;
        int r = w >> 3, cu = w & 7;
        uint32_t sw = (uint32_t)(r * 128 + ((cu * 16) ^ ((r & 7) << 4)));
        const __nv_bfloat16* src = (half ? Ql : Qh) +
            ((size_t)(b * Tv + t0 + r) * Dv + h * HDv + cu * 8);
        cp16(smb + half * 16384 + sw, src, 16u);
    }
    CP_COMMIT;

    auto stageKV = [&](int kc, int st) {
        uint32_t base = smb + AT_KV + st * AT_STAGE;
        #pragma unroll
        for (int j = 0; j < 8; j++) {
            int u = tid + j * 256;      // 0..2047
            int arr = u >> 9;           // 0 Kh, 1 Kl, 2 Vh, 3 Vl
            int w = u & 511;
            int r = w >> 3, cu = w & 7;
            uint32_t sw = (uint32_t)(r * 128 + ((cu * 16) ^ ((r & 7) << 4)));
            const __nv_bfloat16* src;
            if (arr == 0) src = Kh; else if (arr == 1) src = Kl;
            else if (arr == 2) src = Vh; else src = Vl;
            src += (size_t)(b * Tv + kc * 64 + r) * Dv + h * HDv + cu * 8;
            cp16(base + arr * 8192 + sw, src, 16u);
        }
    };
    stageKV(0, 0);
    CP_COMMIT;

    uint32_t qh[4][4], ql[4][4];
    float o[8][4] = {};
    float m0 = -1e30f, m1 = -1e30f, l0 = 0.f, l1 = 0.f;

    const int arow = wid * 16 + (tt & 1) * 8 + rr;
    const int acolb = (tt >> 1) * 16;
    const int brow = (tt >> 1) * 8 + rr;       // + jp*16
    const int bcolb = (tt & 1) * 16;
    const int vrow = (tt & 1) * 8 + rr;        // + ks*16
    const int vcolb = (tt >> 1) * 16;          // + dg*32

    for (int c = 0; c < Tv / 64; c++) {
        if (c + 1 < Tv / 64) { stageKV(c + 1, (c + 1) & 1); CP_COMMIT; CP_WAIT(1); }
        else                 { CP_WAIT(0); }
        __syncthreads();
        if (c == 0) {
            #pragma unroll
            for (int ks = 0; ks < 4; ks++) {
                ldsm4(qh[ks], sm_addr(smb,         arow, acolb + ks * 32));
                ldsm4(ql[ks], sm_addr(smb + 16384, arow, acolb + ks * 32));
            }
        }
        const uint32_t kbase = smb + AT_KV + (c & 1) * AT_STAGE;
        // ---- scores S = Q K^T (pre-scaled) ----
        float accs[8][4] = {};
        #pragma unroll
        for (int ks = 0; ks < 4; ks++) {
            #pragma unroll
            for (int jp = 0; jp < 4; jp++) {
                uint32_t kh4[4], kl4[4];
                ldsm4(kh4, sm_addr(kbase,        brow + jp * 16, bcolb + ks * 32));
                ldsm4(kl4, sm_addr(kbase + 8192, brow + jp * 16, bcolb + ks * 32));
                mma16816(accs[2 * jp],     qh[ks], kh4);
                mma16816(accs[2 * jp + 1], qh[ks], kh4 + 2);
                mma16816(accs[2 * jp],     ql[ks], kh4);
                mma16816(accs[2 * jp + 1], ql[ks], kh4 + 2);
                mma16816(accs[2 * jp],     qh[ks], kl4);
                mma16816(accs[2 * jp + 1], qh[ks], kl4 + 2);
            }
        }
        // ---- online softmax ----
        float mx0 = accs[0][0], mx1 = accs[0][2];
        #pragma unroll
        for (int nj = 0; nj < 8; nj++) {
            mx0 = fmaxf(mx0, fmaxf(accs[nj][0], accs[nj][1]));
            mx1 = fmaxf(mx1, fmaxf(accs[nj][2], accs[nj][3]));
        }
        mx0 = fmaxf(mx0, __shfl_xor_sync(0xffffffffu, mx0, 1));
        mx0 = fmaxf(mx0, __shfl_xor_sync(0xffffffffu, mx0, 2));
        mx1 = fmaxf(mx1, __shfl_xor_sync(0xffffffffu, mx1, 1));
        mx1 = fmaxf(mx1, __shfl_xor_sync(0xffffffffu, mx1, 2));
        float nm0 = fmaxf(m0, mx0), nm1 = fmaxf(m1, mx1);
        float al0 = __expf(m0 - nm0), al1 = __expf(m1 - nm1);
        m0 = nm0; m1 = nm1;
        l0 *= al0; l1 *= al1;
        #pragma unroll
        for (int nj = 0; nj < 8; nj++) {
            o[nj][0] *= al0; o[nj][1] *= al0;
            o[nj][2] *= al1; o[nj][3] *= al1;
        }
        uint32_t pkh[8][2], pkl[8][2];
        #pragma unroll
        for (int nj = 0; nj < 8; nj++) {
            float p0 = __expf(accs[nj][0] - m0), p1 = __expf(accs[nj][1] - m0);
            float p2 = __expf(accs[nj][2] - m1), p3 = __expf(accs[nj][3] - m1);
            l0 += p0 + p1; l1 += p2 + p3;
            float h0 = __bfloat162float(__float2bfloat16(p0));
            float h1 = __bfloat162float(__float2bfloat16(p1));
            float h2 = __bfloat162float(__float2bfloat16(p2));
            float h3 = __bfloat162float(__float2bfloat16(p3));
            pkh[nj][0] = packbf(h0, h1);
            pkh[nj][1] = packbf(h2, h3);
            pkl[nj][0] = packbf(p0 - h0, p1 - h1);
            pkl[nj][1] = packbf(p2 - h2, p3 - h3);
        }
        // ---- O += P V ----
        const uint32_t vbase = kbase + 16384;
        #pragma unroll
        for (int ks = 0; ks < 4; ks++) {
            uint32_t pah[4] = {pkh[2 * ks][0], pkh[2 * ks][1],
                               pkh[2 * ks + 1][0], pkh[2 * ks + 1][1]};
            uint32_t pal[4] = {pkl[2 * ks][0], pkl[2 * ks][1],
                               pkl[2 * ks + 1][0], pkl[2 * ks + 1][1]};
            #pragma unroll
            for (int dg = 0; dg < 4; dg++) {
                uint32_t vh4[4], vl4[4];
                ldsm4t(vh4, sm_addr(vbase,        vrow + ks * 16, vcolb + dg * 32));
                ldsm4t(vl4, sm_addr(vbase + 8192, vrow + ks * 16, vcolb + dg * 32));
                mma16816(o[2 * dg],     pah, vh4);
                mma16816(o[2 * dg + 1], pah, vh4 + 2);
                mma16816(o[2 * dg],     pal, vh4);
                mma16816(o[2 * dg + 1], pal, vh4 + 2);
                mma16816(o[2 * dg],     pah, vl4);
                mma16816(o[2 * dg + 1], pah, vl4 + 2);
            }
        }
        __syncthreads();
    }

    l0 += __shfl_xor_sync(0xffffffffu, l0, 1);
    l0 += __shfl_xor_sync(0xffffffffu, l0, 2);
    l1 += __shfl_xor_sync(0xffffffffu, l1, 1);
    l1 += __shfl_xor_sync(0xffffffffu, l1, 2);
    float i0 = 1.f / l0, i1 = 1.f / l1;

    const int r0 = lane >> 2, c0 = (lane & 3) * 2;
    int tr = t0 + wid * 16 + r0;
    size_t ob0 = (size_t)(b * Tv + tr) * D2v + h * HDv;
    size_t ob1 = ob0 + (size_t)8 * D2v;
    #pragma unroll
    for (int nj = 0; nj < 8; nj++) {
        int d = nj * 8 + c0;
        float v0 = o[nj][0] * i0, v1 = o[nj][1] * i0;
        float v2 = o[nj][2] * i1, v3 = o[nj][3] * i1;
        float h0 = __bfloat162float(__float2bfloat16(v0));
        float h1 = __bfloat162float(__float2bfloat16(v1));
        float h2 = __bfloat162float(__float2bfloat16(v2));
        float h3 = __bfloat162float(__float2bfloat16(v3));
        *(uint32_t*)(Oh + ob0 + d) = packbf(h0, h1);
        *(uint32_t*)(Ol + ob0 + d) = packbf(v0 - h0, v1 - h1);
        *(uint32_t*)(Oh + ob1 + d) = packbf(h2, h3);
        *(uint32_t*)(Ol + ob1 + d) = packbf(v2 - h2, v3 - h3);
    }
}

// ============================================================
// Channel-wise attention (fp32, small). Scattered bf16 hi/lo writes, cols [512,1024).
// ============================================================
__global__ __launch_bounds__(256) void attn_chan(
    const float* __restrict__ Q, const float* __restrict__ K,
    const float* __restrict__ V, __nv_bfloat16* __restrict__ VALh,
    __nv_bfloat16* __restrict__ VALl)
{
    __shared__ float S[64][65];
    __shared__ float buf[64 * 68];

    int h = blockIdx.x, b = blockIdx.y;
    int tid = threadIdx.x;
    int tx = tid & 15, ty = tid >> 4;

    float* Qs = buf;
    float* Ks = buf + 32 * 64;

    float acc[4][4] = {};
    for (int t0 = 0; t0 < Tv; t0 += 32) {
        __syncthreads();
        #pragma unroll
        for (int j2 = 0; j2 < 2; j2++) {
            int j = tid + j2 * 256;
            int r = j >> 4;
            int c = (j & 15) << 2;
            size_t base = ((size_t)b * Tv + t0 + r) * Dv + h * HDv + c;
            *(float4*)&Qs[r * 64 + c] = *(const float4*)(Q + base);
            *(float4*)&Ks[r * 64 + c] = *(const float4*)(K + base);
        }
        __syncthreads();
        #pragma unroll
        for (int r = 0; r < 32; r++) {
            float4 a  = *(const float4*)&Qs[r * 64 + (ty << 2)];
            float4 w4 = *(const float4*)&Ks[r * 64 + (tx << 2)];
            float av[4] = {a.x, a.y, a.z, a.w};
            float wv[4] = {w4.x, w4.y, w4.z, w4.w};
            #pragma unroll
            for (int i = 0; i < 4; i++)
                #pragma unroll
                for (int jj = 0; jj < 4; jj++)
                    acc[i][jj] += av[i] * wv[jj];
        }
    }
    __syncthreads();
    #pragma unroll
    for (int i = 0; i < 4; i++)
        #pragma unroll
        for (int jj = 0; jj < 4; jj++)
            S[(ty << 2) + i][(tx << 2) + jj] = acc[i][jj] * 0.03125f;
    __syncthreads();

    if (tid < 64) {
        float mx = -1e30f;
        #pragma unroll 8
        for (int d = 0; d < 64; d++) mx = fmaxf(mx, S[tid][d]);
        float sum = 0.f;
        #pragma unroll 8
        for (int d = 0; d < 64; d++) { float e = __expf(S[tid][d] - mx); S[tid][d] = e; sum += e; }
        float inv = 1.f / sum;
        #pragma unroll 8
        for (int d = 0; d < 64; d++) S[tid][d] *= inv;
    }
    __syncthreads();

    float* Vst = buf;
    for (int t20 = 0; t20 < Tv; t20 += 64) {
        __syncthreads();
        #pragma unroll
        for (int j2 = 0; j2 < 4; j2++) {
            int j = tid + j2 * 256;
            int r = j >> 4;
            int c = (j & 15) << 2;
            float4 vv = *(const float4*)(V + ((size_t)b * Tv + t20 + r) * Dv + h * HDv + c);
            Vst[(c + 0) * 68 + r] = vv.x; Vst[(c + 1) * 68 + r] = vv.y;
            Vst[(c + 2) * 68 + r] = vv.z; Vst[(c + 3) * 68 + r] = vv.w;
        }
        __syncthreads();
        float o[4][4] = {};
        #pragma unroll
        for (int d = 0; d < 64; d++) {
            float a0 = S[(ty << 2) + 0][d];
            float a1 = S[(ty << 2) + 1][d];
            float a2 = S[(ty << 2) + 2][d];
            float a3 = S[(ty << 2) + 3][d];
            float4 vv = *(const float4*)&Vst[d * 68 + (tx << 2)];
            o[0][0] += a0 * vv.x; o[0][1] += a0 * vv.y; o[0][2] += a0 * vv.z; o[0][3] += a0 * vv.w;
            o[1][0] += a1 * vv.x; o[1][1] += a1 * vv.y; o[1][2] += a1 * vv.z; o[1][3] += a1 * vv.w;
            o[2][0] += a2 * vv.x; o[2][1] += a2 * vv.y; o[2][2] += a2 * vv.z; o[2][3] += a2 * vv.w;
            o[3][0] += a3 * vv.x; o[3][1] += a3 * vv.y; o[3][2] += a3 * vv.z; o[3][3] += a3 * vv.w;
        }
        #pragma unroll
        for (int i = 0; i < 4; i++) {
            int c = (ty << 2) + i;
            #pragma unroll
            for (int jj = 0; jj < 4; jj++) {
                int t2 = t20 + (tx << 2) + jj;
                int t_out = c * 16 + (t2 >> 6);
                int col = ((t2 & 63) << 3) + h;
                size_t idx = ((size_t)b * Tv + t_out) * D2v + Dv + col;
                float v = o[i][jj];
                __nv_bfloat16 hh = __float2bfloat16(v);
                VALh[idx] = hh;
                VALl[idx] = __float2bfloat16(v - __bfloat162float(hh));
            }
        }
    }
}

// ============================================================
// launch
// ============================================================
extern "C" void kernel_launch(void* const* d_in, const int* in_sizes, int n_in,
                              void* d_out, int out_size) {
    const float* x   = (const float*)d_in[0];
    const float* w11 = (const float*)d_in[1];
    const float* b11 = (const float*)d_in[2];
    const float* w12 = (const float*)d_in[3];
    const float* b12 = (const float*)d_in[4];
    const float* w13 = (const float*)d_in[5];
    const float* b13 = (const float*)d_in[6];
    const float* w2  = (const float*)d_in[7];
    const float* b2  = (const float*)d_in[8];
    float* out = (float*)d_out;

    float *q, *k, *v;
    __nv_bfloat16 *xh, *xl, *qh, *ql, *kh, *kl, *vh, *vl, *valh, *vall;
    __nv_bfloat16 *wqh, *wql, *wkh, *wkl, *wvh, *wvl, *w2h, *w2l;
    cudaGetSymbolAddress((void**)&q,    g_q);
    cudaGetSymbolAddress((void**)&k,    g_k);
    cudaGetSymbolAddress((void**)&v,    g_v);
    cudaGetSymbolAddress((void**)&xh,   g_xh);
    cudaGetSymbolAddress((void**)&xl,   g_xl);
    cudaGetSymbolAddress((void**)&qh,   g_qh);
    cudaGetSymbolAddress((void**)&ql,   g_ql);
    cudaGetSymbolAddress((void**)&kh,   g_kh);
    cudaGetSymbolAddress((void**)&kl,   g_kl);
    cudaGetSymbolAddress((void**)&vh,   g_vh);
    cudaGetSymbolAddress((void**)&vl,   g_vl);
    cudaGetSymbolAddress((void**)&valh, g_valh);
    cudaGetSymbolAddress((void**)&vall, g_vall);
    cudaGetSymbolAddress((void**)&wqh,  g_wqh);
    cudaGetSymbolAddress((void**)&wql,  g_wql);
    cudaGetSymbolAddress((void**)&wkh,  g_wkh);
    cudaGetSymbolAddress((void**)&wkl,  g_wkl);
    cudaGetSymbolAddress((void**)&wvh,  g_wvh);
    cudaGetSymbolAddress((void**)&wvl,  g_wvl);
    cudaGetSymbolAddress((void**)&w2h,  g_w2h);
    cudaGetSymbolAddress((void**)&w2l,  g_w2l);

    cudaFuncSetAttribute(conv_hmma<Dv, true, true>,
                         cudaFuncAttributeMaxDynamicSharedMemorySize, SMEM_TOTAL);
    cudaFuncSetAttribute(conv_hmma<D2v, true, false>,
                         cudaFuncAttributeMaxDynamicSharedMemorySize, SMEM_TOTAL);
    cudaFuncSetAttribute(attn_time_hmma,
                         cudaFuncAttributeMaxDynamicSharedMemorySize, AT_SMEM);

    int nx = Bv * Tv * Dv;
    split_f32<<<(nx + 255) / 256, 256>>>(x, xh, xl, nx);
    int tot1 = 3 * Dv * Dv;
    repack_wsplit<<<(tot1 + 255) / 256, 256>>>(w11, wqh, wql, Dv);
    repack_wsplit<<<(tot1 + 255) / 256, 256>>>(w12, wkh, wkl, Dv);
    repack_wsplit<<<(tot1 + 255) / 256, 256>>>(w13, wvh, wvl, Dv);
    int tot2 = 3 * D2v * Dv;
    repack_wsplit<<<(tot2 + 255) / 256, 256>>>(w2, w2h, w2l, D2v);

    dim3 gconv(Tv / 128, Dv / 128, Bv);
    conv_hmma<Dv, true, true><<<gconv, 256, SMEM_TOTAL>>>(xh, xl, wqh, wql, b11, q,
                                                          qh, ql, 0.125f);
    conv_hmma<Dv, true, true><<<gconv, 256, SMEM_TOTAL>>>(xh, xl, wkh, wkl, b12, k,
                                                          kh, kl, 1.0f);
    conv_hmma<Dv, true, true><<<gconv, 256, SMEM_TOTAL>>>(xh, xl, wvh, wvl, b13, v,
                                                          vh, vl, 1.0f);

    attn_time_hmma<<<dim3(Tv / 128, Hv, Bv), 256, AT_SMEM>>>(qh, ql, kh, kl, vh, vl,
                                                             valh, vall);
    attn_chan<<<dim3(Hv, Bv), 256>>>(q, k, v, valh, vall);

    conv_hmma<D2v, true, false><<<gconv, 256, SMEM_TOTAL>>>(valh, vall, w2h, w2l, b2, out,
                                                            nullptr, nullptr, 1.0f);
}

// round 7
// speedup vs baseline: 3.1071x; 1.1354x over previous
#include <cuda_runtime.h>
#include <cuda_bf16.h>
#include <cstdint>

// ---- problem dims ----
#define Bv   8
#define Tv   1024
#define Dv   512
#define Hv   8
#define HDv  64
#define D2v  1024

// ---- scratch ----
__device__ __nv_bfloat16 g_xh[Bv * Tv * Dv];
__device__ __nv_bfloat16 g_xl[Bv * Tv * Dv];
__device__ __nv_bfloat16 g_qh[Bv * Tv * Dv];   // pre-scaled by 0.125
__device__ __nv_bfloat16 g_ql[Bv * Tv * Dv];
__device__ __nv_bfloat16 g_kh[Bv * Tv * Dv];
__device__ __nv_bfloat16 g_kl[Bv * Tv * Dv];
__device__ __nv_bfloat16 g_vh[Bv * Tv * Dv];
__device__ __nv_bfloat16 g_vl[Bv * Tv * Dv];
__device__ __nv_bfloat16 g_valh[Bv * Tv * D2v];
__device__ __nv_bfloat16 g_vall[Bv * Tv * D2v];
__device__ float g_chanA[Bv * Hv * 64 * 64];
__device__ __nv_bfloat16 g_wqh[3 * Dv * Dv];
__device__ __nv_bfloat16 g_wql[3 * Dv * Dv];
__device__ __nv_bfloat16 g_wkh[3 * Dv * Dv];
__device__ __nv_bfloat16 g_wkl[3 * Dv * Dv];
__device__ __nv_bfloat16 g_wvh[3 * Dv * Dv];
__device__ __nv_bfloat16 g_wvl[3 * Dv * Dv];
__device__ __nv_bfloat16 g_w2h[3 * D2v * Dv];
__device__ __nv_bfloat16 g_w2l[3 * D2v * Dv];

// ============================================================
// helpers (sm_80-baseline PTX only)
// ============================================================
__device__ __forceinline__ uint32_t smem_u32(const void* p) {
    uint32_t a;
    asm("{ .reg .u64 t; cvta.to.shared.u64 t, %1; cvt.u32.u64 %0, t; }"
        : "=r"(a) : "l"(p));
    return a;
}

__device__ __forceinline__ void ldsm4(uint32_t* r, uint32_t addr) {
    asm volatile("ldmatrix.sync.aligned.m8n8.x4.shared.b16 {%0,%1,%2,%3}, [%4];"
                 : "=r"(r[0]), "=r"(r[1]), "=r"(r[2]), "=r"(r[3]) : "r"(addr));
}
__device__ __forceinline__ void ldsm4t(uint32_t* r, uint32_t addr) {
    asm volatile("ldmatrix.sync.aligned.m8n8.x4.trans.shared.b16 {%0,%1,%2,%3}, [%4];"
                 : "=r"(r[0]), "=r"(r[1]), "=r"(r[2]), "=r"(r[3]) : "r"(addr));
}

__device__ __forceinline__ void mma16816(float* c, const uint32_t* a, const uint32_t* b) {
    asm volatile(
        "mma.sync.aligned.m16n8k16.row.col.f32.bf16.bf16.f32 "
        "{%0,%1,%2,%3}, {%4,%5,%6,%7}, {%8,%9}, {%0,%1,%2,%3};"
        : "+f"(c[0]), "+f"(c[1]), "+f"(c[2]), "+f"(c[3])
        : "r"(a[0]), "r"(a[1]), "r"(a[2]), "r"(a[3]), "r"(b[0]), "r"(b[1]));
}

__device__ __forceinline__ void cp16(uint32_t dst, const void* src, uint32_t n) {
    asm volatile("cp.async.cg.shared.global [%0], [%1], 16, %2;"
                 :: "r"(dst), "l"(__cvta_generic_to_global(src)), "r"(n));
}
#define CP_COMMIT  asm volatile("cp.async.commit_group;" ::: "memory")
#define CP_WAIT(n) asm volatile("cp.async.wait_group %0;" :: "n"(n) : "memory")

__device__ __forceinline__ uint32_t packbf(float lo, float hi) {
    uint32_t r;
    asm("cvt.rn.bf16x2.f32 %0, %1, %2;" : "=r"(r) : "f"(hi), "f"(lo));
    return r;
}

__device__ __forceinline__ uint32_t sm_addr(uint32_t base, int row, int col) {
    return base + (uint32_t)(row * 128 + (col ^ ((row & 7) << 4)));
}

// reconstruct 2 floats from bf16x2 hi + lo words
__device__ __forceinline__ float2 rec2(uint32_t hw, uint32_t lw) {
    float2 fh = __bfloat1622float2(*(__nv_bfloat162*)&hw);
    float2 fl = __bfloat1622float2(*(__nv_bfloat162*)&lw);
    return make_float2(fh.x + fl.x, fh.y + fl.y);
}

// ============================================================
// transforms
// ============================================================
__global__ void split_f32(const float* __restrict__ x, __nv_bfloat16* __restrict__ hi,
                          __nv_bfloat16* __restrict__ lo, int n) {
    int i = blockIdx.x * 256 + threadIdx.x;
    if (i >= n) return;
    float v = x[i];
    __nv_bfloat16 h = __float2bfloat16(v);
    hi[i] = h;
    lo[i] = __float2bfloat16(v - __bfloat162float(h));
}

__global__ void repack_wsplit(const float* __restrict__ w, __nv_bfloat16* __restrict__ hi,
                              __nv_bfloat16* __restrict__ lo, int cin) {
    int idx = blockIdx.x * 256 + threadIdx.x;
    int total = 3 * cin * Dv;
    if (idx >= total) return;
    int kk = idx % (3 * cin);
    int co = idx / (3 * cin);
    int tap = kk / cin;
    int ci  = kk - tap * cin;
    float v = w[((size_t)co * cin + ci) * 3 + tap];
    __nv_bfloat16 h = __float2bfloat16(v);
    hi[idx] = h;
    lo[idx] = __float2bfloat16(v - __bfloat162float(h));
}

// ============================================================
// conv1d(k=3,'same') + bias + ReLU via mma.sync bf16x3.
// CTA tile 256(t) x 128(co); warp tile 64x64 (warps 4m x 2n).
// K in 64-element chunks, 2-stage cp.async.
// TRIPLE: fused Q/K/V (blockIdx.z = b + 8*which), outputs split bf16.
// else: single conv (conv2), fp32 output.
// ============================================================
#define ST2        98304     // Ah 32K | Al 32K | Bh 16K | Bl 16K
#define SMEM_TOT2  (2 * ST2) // 192 KB

template <int CIN, bool TRIPLE>
__global__ __launch_bounds__(256, 1)
void conv_mma2(const __nv_bfloat16* __restrict__ Xh, const __nv_bfloat16* __restrict__ Xl,
               const __nv_bfloat16* __restrict__ Wh0, const __nv_bfloat16* __restrict__ Wl0,
               const __nv_bfloat16* __restrict__ Wh1, const __nv_bfloat16* __restrict__ Wl1,
               const __nv_bfloat16* __restrict__ Wh2, const __nv_bfloat16* __restrict__ Wl2,
               const float* __restrict__ bias0, const float* __restrict__ bias1,
               const float* __restrict__ bias2,
               __nv_bfloat16* __restrict__ Yh0, __nv_bfloat16* __restrict__ Yl0,
               __nv_bfloat16* __restrict__ Yh1, __nv_bfloat16* __restrict__ Yl1,
               __nv_bfloat16* __restrict__ Yh2, __nv_bfloat16* __restrict__ Yl2,
               float* __restrict__ Yf) {
    extern __shared__ __align__(1024) char sm[];
    const uint32_t smb = smem_u32(sm);
    const int tid = threadIdx.x;
    const int b     = TRIPLE ? (blockIdx.z & 7) : blockIdx.z;
    const int which = TRIPLE ? (blockIdx.z >> 3) : 0;
    const int t0 = blockIdx.x * 256;
    const int n0 = blockIdx.y * 128;
    constexpr int KTOT = 3 * CIN;
    constexpr int C = KTOT / 64;

    const __nv_bfloat16* Wh = (which == 0) ? Wh0 : (which == 1) ? Wh1 : Wh2;
    const __nv_bfloat16* Wl = (which == 0) ? Wl0 : (which == 1) ? Wl1 : Wl2;
    const float* bias = (which == 0) ? bias0 : (which == 1) ? bias1 : bias2;

    const int lane = tid & 31, wid = tid >> 5;
    const int wm = wid & 3, wn = wid >> 2;
    const int rr = lane & 7, tt = lane >> 3;
    const int arow = wm * 64 + (tt & 1) * 8 + rr;
    const int acol = (tt >> 1) * 16;
    const int brow = wn * 64 + (tt >> 1) * 8 + rr;
    const int bcol = (tt & 1) * 16;

    float acc[4][8][4] = {};

    auto stage = [&](int c, int st) {
        const int kb  = c * 64;
        const int tap = kb / CIN;
        const int cb  = kb - tap * CIN;
        const int dt  = tap - 1;
        uint32_t base = smb + st * ST2;
        // A: 256 rows x 128B, hi + lo
        #pragma unroll
        for (int j = 0; j < 16; j++) {
            int half = j >> 3;
            int u = tid + (j & 7) * 256;     // 0..2047
            int r = u >> 3, cu = u & 7;      // r 0..255
            uint32_t sw = (uint32_t)(r * 128 + ((cu * 16) ^ ((r & 7) << 4)));
            int tg = t0 + r + dt;
            uint32_t ok = (tg >= 0 && tg < Tv) ? 16u : 0u;
            int tc = min(max(tg, 0), Tv - 1);
            const __nv_bfloat16* src = (half ? Xl : Xh) +
                ((size_t)(b * Tv + tc) * CIN + cb + cu * 8);
            cp16(base + half * 32768 + sw, src, ok);
        }
        // B: 128 rows x 128B, hi + lo
        #pragma unroll
        for (int j = 0; j < 8; j++) {
            int half = j >> 2;
            int u = tid + (j & 3) * 256;     // 0..1023
            int r = u >> 3, cu = u & 7;      // r 0..127
            uint32_t sw = (uint32_t)(r * 128 + ((cu * 16) ^ ((r & 7) << 4)));
            const __nv_bfloat16* src = (half ? Wl : Wh) +
                ((size_t)(n0 + r) * KTOT + kb + cu * 8);
            cp16(base + 65536 + half * 16384 + sw, src, 16u);
        }
    };

    auto compute = [&](int st) {
        const uint32_t ah_b = smb + st * ST2;
        const uint32_t al_b = ah_b + 32768;
        const uint32_t bh_b = ah_b + 65536;
        const uint32_t bl_b = ah_b + 81920;
        #pragma unroll
        for (int ks = 0; ks < 4; ks++) {
            uint32_t Ah[4][4], Al[4][4], Bh[8][2], Bl[8][2];
            #pragma unroll
            for (int mi = 0; mi < 4; mi++) {
                ldsm4(Ah[mi], sm_addr(ah_b, arow + mi * 16, acol + ks * 32));
                ldsm4(Al[mi], sm_addr(al_b, arow + mi * 16, acol + ks * 32));
            }
            #pragma unroll
            for (int jp = 0; jp < 4; jp++) {
                uint32_t r4[4];
                ldsm4(r4, sm_addr(bh_b, brow + jp * 16, bcol + ks * 32));
                Bh[2 * jp][0] = r4[0]; Bh[2 * jp][1] = r4[1];
                Bh[2 * jp + 1][0] = r4[2]; Bh[2 * jp + 1][1] = r4[3];
                ldsm4(r4, sm_addr(bl_b, brow + jp * 16, bcol + ks * 32));
                Bl[2 * jp][0] = r4[0]; Bl[2 * jp][1] = r4[1];
                Bl[2 * jp + 1][0] = r4[2]; Bl[2 * jp + 1][1] = r4[3];
            }
            #pragma unroll
            for (int mi = 0; mi < 4; mi++)
                #pragma unroll
                for (int nj = 0; nj < 8; nj++) {
                    mma16816(acc[mi][nj], Ah[mi], Bh[nj]);
                    mma16816(acc[mi][nj], Al[mi], Bh[nj]);
                    mma16816(acc[mi][nj], Ah[mi], Bl[nj]);
                }
        }
    };

    stage(0, 0);
    CP_COMMIT;
    for (int c = 0; c < C; c++) {
        if (c + 1 < C) { stage(c + 1, (c + 1) & 1); CP_COMMIT; CP_WAIT(1); }
        else           { CP_WAIT(0); }
        __syncthreads();
        compute(c & 1);
        __syncthreads();
    }

    const int r0 = lane >> 2;
    const int c0 = (lane & 3) * 2;
    if (TRIPLE) {
        __nv_bfloat16* Yh = (which == 0) ? Yh0 : (which == 1) ? Yh1 : Yh2;
        __nv_bfloat16* Yl = (which == 0) ? Yl0 : (which == 1) ? Yl1 : Yl2;
        const float oscale = (which == 0) ? 0.125f : 1.0f;
        #pragma unroll
        for (int mi = 0; mi < 4; mi++) {
            int mg = t0 + wm * 64 + mi * 16 + r0;
            size_t ro0 = (size_t)(b * Tv + mg) * Dv;
            size_t ro1 = (size_t)(b * Tv + mg + 8) * Dv;
            #pragma unroll
            for (int nj = 0; nj < 8; nj++) {
                int ng = n0 + wn * 64 + nj * 8 + c0;
                float2 bv = *(const float2*)(bias + ng);
                float v0 = fmaxf(acc[mi][nj][0] + bv.x, 0.f) * oscale;
                float v1 = fmaxf(acc[mi][nj][1] + bv.y, 0.f) * oscale;
                float v2 = fmaxf(acc[mi][nj][2] + bv.x, 0.f) * oscale;
                float v3 = fmaxf(acc[mi][nj][3] + bv.y, 0.f) * oscale;
                float h0 = __bfloat162float(__float2bfloat16(v0));
                float h1 = __bfloat162float(__float2bfloat16(v1));
                float h2 = __bfloat162float(__float2bfloat16(v2));
                float h3 = __bfloat162float(__float2bfloat16(v3));
                *(uint32_t*)(Yh + ro0 + ng) = packbf(h0, h1);
                *(uint32_t*)(Yl + ro0 + ng) = packbf(v0 - h0, v1 - h1);
                *(uint32_t*)(Yh + ro1 + ng) = packbf(h2, h3);
                *(uint32_t*)(Yl + ro1 + ng) = packbf(v2 - h2, v3 - h3);
            }
        }
    } else {
        #pragma unroll
        for (int mi = 0; mi < 4; mi++) {
            int mg = t0 + wm * 64 + mi * 16 + r0;
            float* y0 = Yf + (size_t)(b * Tv + mg) * Dv;
            float* y1 = Yf + (size_t)(b * Tv + mg + 8) * Dv;
            #pragma unroll
            for (int nj = 0; nj < 8; nj++) {
                int ng = n0 + wn * 64 + nj * 8 + c0;
                float2 bv = *(const float2*)(bias + ng);
                float v0 = fmaxf(acc[mi][nj][0] + bv.x, 0.f);
                float v1 = fmaxf(acc[mi][nj][1] + bv.y, 0.f);
                float v2 = fmaxf(acc[mi][nj][2] + bv.x, 0.f);
                float v3 = fmaxf(acc[mi][nj][3] + bv.y, 0.f);
                *(float2*)(y0 + ng) = make_float2(v0, v1);
                *(float2*)(y1 + ng) = make_float2(v2, v3);
            }
        }
    }
}

// ============================================================
// Time-wise flash attention via mma.sync bf16x3 (proven R4 kernel).
// ============================================================
#define AT_STAGE 32768
#define AT_KV    32768
#define AT_SMEM  (AT_KV + 2 * AT_STAGE)

__global__ __launch_bounds__(256, 1)
void attn_time_hmma(const __nv_bfloat16* __restrict__ Qh, const __nv_bfloat16* __restrict__ Ql,
                    const __nv_bfloat16* __restrict__ Kh, const __nv_bfloat16* __restrict__ Kl,
                    const __nv_bfloat16* __restrict__ Vh, const __nv_bfloat16* __restrict__ Vl,
                    __nv_bfloat16* __restrict__ Oh, __nv_bfloat16* __restrict__ Ol) {
    extern __shared__ __align__(1024) char sm[];
    const uint32_t smb = smem_u32(sm);
    const int tid = threadIdx.x, lane = tid & 31, wid = tid >> 5;
    const int b = blockIdx.z, h = blockIdx.y, t0 = blockIdx.x * 128;
    const int rr = lane & 7, tt = lane >> 3;

    #pragma unroll
    for (int j = 0; j < 8; j++) {
        int u = tid + j * 256;
        int half = u >> 10;
        int w = u & 1023;
        int r = w >> 3, cu = w & 7;
        uint32_t sw = (uint32_t)(r * 128 + ((cu * 16) ^ ((r & 7) << 4)));
        const __nv_bfloat16* src = (half ? Ql : Qh) +
            ((size_t)(b * Tv + t0 + r) * Dv + h * HDv + cu * 8);
        cp16(smb + half * 16384 + sw, src, 16u);
    }
    CP_COMMIT;

    auto stageKV = [&](int kc, int st) {
        uint32_t base = smb + AT_KV + st * AT_STAGE;
        #pragma unroll
        for (int j = 0; j < 8; j++) {
            int u = tid + j * 256;
            int arr = u >> 9;
            int w = u & 511;
            int r = w >> 3, cu = w & 7;
            uint32_t sw = (uint32_t)(r * 128 + ((cu * 16) ^ ((r & 7) << 4)));
            const __nv_bfloat16* src;
            if (arr == 0) src = Kh; else if (arr == 1) src = Kl;
            else if (arr == 2) src = Vh; else src = Vl;
            src += (size_t)(b * Tv + kc * 64 + r) * Dv + h * HDv + cu * 8;
            cp16(base + arr * 8192 + sw, src, 16u);
        }
    };
    stageKV(0, 0);
    CP_COMMIT;

    uint32_t qh[4][4], ql[4][4];
    float o[8][4] = {};
    float m0 = -1e30f, m1 = -1e30f, l0 = 0.f, l1 = 0.f;

    const int arow = wid * 16 + (tt & 1) * 8 + rr;
    const int acolb = (tt >> 1) * 16;
    const int brow = (tt >> 1) * 8 + rr;
    const int bcolb = (tt & 1) * 16;
    const int vrow = (tt & 1) * 8 + rr;
    const int vcolb = (tt >> 1) * 16;

    for (int c = 0; c < Tv / 64; c++) {
        if (c + 1 < Tv / 64) { stageKV(c + 1, (c + 1) & 1); CP_COMMIT; CP_WAIT(1); }
        else                 { CP_WAIT(0); }
        __syncthreads();
        if (c == 0) {
            #pragma unroll
            for (int ks = 0; ks < 4; ks++) {
                ldsm4(qh[ks], sm_addr(smb,         arow, acolb + ks * 32));
                ldsm4(ql[ks], sm_addr(smb + 16384, arow, acolb + ks * 32));
            }
        }
        const uint32_t kbase = smb + AT_KV + (c & 1) * AT_STAGE;
        float accs[8][4] = {};
        #pragma unroll
        for (int ks = 0; ks < 4; ks++) {
            #pragma unroll
            for (int jp = 0; jp < 4; jp++) {
                uint32_t kh4[4], kl4[4];
                ldsm4(kh4, sm_addr(kbase,        brow + jp * 16, bcolb + ks * 32));
                ldsm4(kl4, sm_addr(kbase + 8192, brow + jp * 16, bcolb + ks * 32));
                mma16816(accs[2 * jp],     qh[ks], kh4);
                mma16816(accs[2 * jp + 1], qh[ks], kh4 + 2);
                mma16816(accs[2 * jp],     ql[ks], kh4);
                mma16816(accs[2 * jp + 1], ql[ks], kh4 + 2);
                mma16816(accs[2 * jp],     qh[ks], kl4);
                mma16816(accs[2 * jp + 1], qh[ks], kl4 + 2);
            }
        }
        float mx0 = accs[0][0], mx1 = accs[0][2];
        #pragma unroll
        for (int nj = 0; nj < 8; nj++) {
            mx0 = fmaxf(mx0, fmaxf(accs[nj][0], accs[nj][1]));
            mx1 = fmaxf(mx1, fmaxf(accs[nj][2], accs[nj][3]));
        }
        mx0 = fmaxf(mx0, __shfl_xor_sync(0xffffffffu, mx0, 1));
        mx0 = fmaxf(mx0, __shfl_xor_sync(0xffffffffu, mx0, 2));
        mx1 = fmaxf(mx1, __shfl_xor_sync(0xffffffffu, mx1, 1));
        mx1 = fmaxf(mx1, __shfl_xor_sync(0xffffffffu, mx1, 2));
        float nm0 = fmaxf(m0, mx0), nm1 = fmaxf(m1, mx1);
        float al0 = __expf(m0 - nm0), al1 = __expf(m1 - nm1);
        m0 = nm0; m1 = nm1;
        l0 *= al0; l1 *= al1;
        #pragma unroll
        for (int nj = 0; nj < 8; nj++) {
            o[nj][0] *= al0; o[nj][1] *= al0;
            o[nj][2] *= al1; o[nj][3] *= al1;
        }
        uint32_t pkh[8][2], pkl[8][2];
        #pragma unroll
        for (int nj = 0; nj < 8; nj++) {
            float p0 = __expf(accs[nj][0] - m0), p1 = __expf(accs[nj][1] - m0);
            float p2 = __expf(accs[nj][2] - m1), p3 = __expf(accs[nj][3] - m1);
            l0 += p0 + p1; l1 += p2 + p3;
            float h0 = __bfloat162float(__float2bfloat16(p0));
            float h1 = __bfloat162float(__float2bfloat16(p1));
            float h2 = __bfloat162float(__float2bfloat16(p2));
            float h3 = __bfloat162float(__float2bfloat16(p3));
            pkh[nj][0] = packbf(h0, h1);
            pkh[nj][1] = packbf(h2, h3);
            pkl[nj][0] = packbf(p0 - h0, p1 - h1);
            pkl[nj][1] = packbf(p2 - h2, p3 - h3);
        }
        const uint32_t vbase = kbase + 16384;
        #pragma unroll
        for (int ks = 0; ks < 4; ks++) {
            uint32_t pah[4] = {pkh[2 * ks][0], pkh[2 * ks][1],
                               pkh[2 * ks + 1][0], pkh[2 * ks + 1][1]};
            uint32_t pal[4] = {pkl[2 * ks][0], pkl[2 * ks][1],
                               pkl[2 * ks + 1][0], pkl[2 * ks + 1][1]};
            #pragma unroll
            for (int dg = 0; dg < 4; dg++) {
                uint32_t vh4[4], vl4[4];
                ldsm4t(vh4, sm_addr(vbase,        vrow + ks * 16, vcolb + dg * 32));
                ldsm4t(vl4, sm_addr(vbase + 8192, vrow + ks * 16, vcolb + dg * 32));
                mma16816(o[2 * dg],     pah, vh4);
                mma16816(o[2 * dg + 1], pah, vh4 + 2);
                mma16816(o[2 * dg],     pal, vh4);
                mma16816(o[2 * dg + 1], pal, vh4 + 2);
                mma16816(o[2 * dg],     pah, vl4);
                mma16816(o[2 * dg + 1], pah, vl4 + 2);
            }
        }
        __syncthreads();
    }

    l0 += __shfl_xor_sync(0xffffffffu, l0, 1);
    l0 += __shfl_xor_sync(0xffffffffu, l0, 2);
    l1 += __shfl_xor_sync(0xffffffffu, l1, 1);
    l1 += __shfl_xor_sync(0xffffffffu, l1, 2);
    float i0 = 1.f / l0, i1 = 1.f / l1;

    const int r0 = lane >> 2, c0 = (lane & 3) * 2;
    int tr = t0 + wid * 16 + r0;
    size_t ob0 = (size_t)(b * Tv + tr) * D2v + h * HDv;
    size_t ob1 = ob0 + (size_t)8 * D2v;
    #pragma unroll
    for (int nj = 0; nj < 8; nj++) {
        int d = nj * 8 + c0;
        float v0 = o[nj][0] * i0, v1 = o[nj][1] * i0;
        float v2 = o[nj][2] * i1, v3 = o[nj][3] * i1;
        float h0 = __bfloat162float(__float2bfloat16(v0));
        float h1 = __bfloat162float(__float2bfloat16(v1));
        float h2 = __bfloat162float(__float2bfloat16(v2));
        float h3 = __bfloat162float(__float2bfloat16(v3));
        *(uint32_t*)(Oh + ob0 + d) = packbf(h0, h1);
        *(uint32_t*)(Ol + ob0 + d) = packbf(v0 - h0, v1 - h1);
        *(uint32_t*)(Oh + ob1 + d) = packbf(h2, h3);
        *(uint32_t*)(Ol + ob1 + d) = packbf(v2 - h2, v3 - h3);
    }
}

// ============================================================
// Channel attention part 1: S = (Qs^T K)/4 per (b,h), softmax rows,
// write A to global. Q/K reconstructed from bf16 hi/lo (Q pre-scaled 1/8).
// ============================================================
__global__ __launch_bounds__(256) void attn_chan_s(
    const __nv_bfloat16* __restrict__ Qh, const __nv_bfloat16* __restrict__ Ql,
    const __nv_bfloat16* __restrict__ Kh, const __nv_bfloat16* __restrict__ Kl,
    float* __restrict__ Aout)
{
    __shared__ float S[64][65];
    __shared__ float Qs[32 * 64];
    __shared__ float Ks[32 * 64];

    int h = blockIdx.x, b = blockIdx.y;
    int tid = threadIdx.x;
    int tx = tid & 15, ty = tid >> 4;

    float acc[4][4] = {};
    for (int t0 = 0; t0 < Tv; t0 += 32) {
        __syncthreads();
        #pragma unroll
        for (int j2 = 0; j2 < 4; j2++) {
            int j = tid + j2 * 256;          // 0..1023
            int r = j >> 5;                  // 0..31
            int c2 = (j & 31) * 2;           // 0..62
            size_t base = (size_t)(b * Tv + t0 + r) * Dv + h * HDv + c2;
            float2 fq = rec2(*(const uint32_t*)(Qh + base), *(const uint32_t*)(Ql + base));
            float2 fk = rec2(*(const uint32_t*)(Kh + base), *(const uint32_t*)(Kl + base));
            Qs[r * 64 + c2] = fq.x; Qs[r * 64 + c2 + 1] = fq.y;
            Ks[r * 64 + c2] = fk.x; Ks[r * 64 + c2 + 1] = fk.y;
        }
        __syncthreads();
        #pragma unroll
        for (int r = 0; r < 32; r++) {
            float4 a  = *(const float4*)&Qs[r * 64 + (ty << 2)];
            float4 w4 = *(const float4*)&Ks[r * 64 + (tx << 2)];
            float av[4] = {a.x, a.y, a.z, a.w};
            float wv[4] = {w4.x, w4.y, w4.z, w4.w};
            #pragma unroll
            for (int i = 0; i < 4; i++)
                #pragma unroll
                for (int jj = 0; jj < 4; jj++)
                    acc[i][jj] += av[i] * wv[jj];
        }
    }
    __syncthreads();
    #pragma unroll
    for (int i = 0; i < 4; i++)
        #pragma unroll
        for (int jj = 0; jj < 4; jj++)
            S[(ty << 2) + i][(tx << 2) + jj] = acc[i][jj] * 0.25f; // (1/32)*8
    __syncthreads();

    if (tid < 64) {
        float mx = -1e30f;
        #pragma unroll 8
        for (int d = 0; d < 64; d++) mx = fmaxf(mx, S[tid][d]);
        float sum = 0.f;
        #pragma unroll 8
        for (int d = 0; d < 64; d++) { float e = __expf(S[tid][d] - mx); S[tid][d] = e; sum += e; }
        float inv = 1.f / sum;
        #pragma unroll 8
        for (int d = 0; d < 64; d++) S[tid][d] *= inv;
    }
    __syncthreads();

    float* ap = Aout + (size_t)(b * Hv + h) * 4096;
    #pragma unroll
    for (int j2 = 0; j2 < 16; j2++) {
        int j = tid + j2 * 256;
        ap[j] = S[j >> 6][j & 63];
    }
}

// ============================================================
// Channel attention part 2: O[c,t2] = sum_d A[c,d] v[t2,d], scattered
// torch-reshape write. grid (H, B, 4) — each z handles 256 t2.
// ============================================================
__global__ __launch_bounds__(256) void attn_chan_av(
    const __nv_bfloat16* __restrict__ Vh, const __nv_bfloat16* __restrict__ Vl,
    const float* __restrict__ Ain,
    __nv_bfloat16* __restrict__ VALh, __nv_bfloat16* __restrict__ VALl)
{
    __shared__ float As[64][65];
    __shared__ float Vst[64 * 68];

    int h = blockIdx.x, b = blockIdx.y, zc = blockIdx.z;
    int tid = threadIdx.x;
    int tx = tid & 15, ty = tid >> 4;

    const float* ap = Ain + (size_t)(b * Hv + h) * 4096;
    #pragma unroll
    for (int j2 = 0; j2 < 16; j2++) {
        int j = tid + j2 * 256;
        As[j >> 6][j & 63] = ap[j];
    }

    for (int sub = 0; sub < 4; sub++) {
        int t20 = zc * 256 + sub * 64;
        __syncthreads();
        #pragma unroll
        for (int j2 = 0; j2 < 8; j2++) {
            int j = tid + j2 * 256;          // 0..2047
            int r = j >> 5;                  // t2 local 0..63
            int c2 = (j & 31) * 2;           // d
            size_t base = (size_t)(b * Tv + t20 + r) * Dv + h * HDv + c2;
            float2 fv = rec2(*(const uint32_t*)(Vh + base), *(const uint32_t*)(Vl + base));
            Vst[(c2 + 0) * 68 + r] = fv.x;
            Vst[(c2 + 1) * 68 + r] = fv.y;
        }
        __syncthreads();
        float o[4][4] = {};
        #pragma unroll
        for (int d = 0; d < 64; d++) {
            float a0 = As[(ty << 2) + 0][d];
            float a1 = As[(ty << 2) + 1][d];
            float a2 = As[(ty << 2) + 2][d];
            float a3 = As[(ty << 2) + 3][d];
            float4 vv = *(const float4*)&Vst[d * 68 + (tx << 2)];
            o[0][0] += a0 * vv.x; o[0][1] += a0 * vv.y; o[0][2] += a0 * vv.z; o[0][3] += a0 * vv.w;
            o[1][0] += a1 * vv.x; o[1][1] += a1 * vv.y; o[1][2] += a1 * vv.z; o[1][3] += a1 * vv.w;
            o[2][0] += a2 * vv.x; o[2][1] += a2 * vv.y; o[2][2] += a2 * vv.z; o[2][3] += a2 * vv.w;
            o[3][0] += a3 * vv.x; o[3][1] += a3 * vv.y; o[3][2] += a3 * vv.z; o[3][3] += a3 * vv.w;
        }
        #pragma unroll
        for (int i = 0; i < 4; i++) {
            int c = (ty << 2) + i;
            #pragma unroll
            for (int jj = 0; jj < 4; jj++) {
                int t2 = t20 + (tx << 2) + jj;
                int t_out = c * 16 + (t2 >> 6);
                int col = ((t2 & 63) << 3) + h;
                size_t idx = (size_t)(b * Tv + t_out) * D2v + Dv + col;
                float v = o[i][jj];
                __nv_bfloat16 hh = __float2bfloat16(v);
                VALh[idx] = hh;
                VALl[idx] = __float2bfloat16(v - __bfloat162float(hh));
            }
        }
    }
}

// ============================================================
// launch
// ============================================================
extern "C" void kernel_launch(void* const* d_in, const int* in_sizes, int n_in,
                              void* d_out, int out_size) {
    const float* x   = (const float*)d_in[0];
    const float* w11 = (const float*)d_in[1];
    const float* b11 = (const float*)d_in[2];
    const float* w12 = (const float*)d_in[3];
    const float* b12 = (const float*)d_in[4];
    const float* w13 = (const float*)d_in[5];
    const float* b13 = (const float*)d_in[6];
    const float* w2  = (const float*)d_in[7];
    const float* b2  = (const float*)d_in[8];
    float* out = (float*)d_out;

    __nv_bfloat16 *xh, *xl, *qh, *ql, *kh, *kl, *vh, *vl, *valh, *vall;
    __nv_bfloat16 *wqh, *wql, *wkh, *wkl, *wvh, *wvl, *w2h, *w2l;
    float* chanA;
    cudaGetSymbolAddress((void**)&xh,   g_xh);
    cudaGetSymbolAddress((void**)&xl,   g_xl);
    cudaGetSymbolAddress((void**)&qh,   g_qh);
    cudaGetSymbolAddress((void**)&ql,   g_ql);
    cudaGetSymbolAddress((void**)&kh,   g_kh);
    cudaGetSymbolAddress((void**)&kl,   g_kl);
    cudaGetSymbolAddress((void**)&vh,   g_vh);
    cudaGetSymbolAddress((void**)&vl,   g_vl);
    cudaGetSymbolAddress((void**)&valh, g_valh);
    cudaGetSymbolAddress((void**)&vall, g_vall);
    cudaGetSymbolAddress((void**)&chanA, g_chanA);
    cudaGetSymbolAddress((void**)&wqh,  g_wqh);
    cudaGetSymbolAddress((void**)&wql,  g_wql);
    cudaGetSymbolAddress((void**)&wkh,  g_wkh);
    cudaGetSymbolAddress((void**)&wkl,  g_wkl);
    cudaGetSymbolAddress((void**)&wvh,  g_wvh);
    cudaGetSymbolAddress((void**)&wvl,  g_wvl);
    cudaGetSymbolAddress((void**)&w2h,  g_w2h);
    cudaGetSymbolAddress((void**)&w2l,  g_w2l);

    cudaFuncSetAttribute(conv_mma2<Dv, true>,
                         cudaFuncAttributeMaxDynamicSharedMemorySize, SMEM_TOT2);
    cudaFuncSetAttribute(conv_mma2<D2v, false>,
                         cudaFuncAttributeMaxDynamicSharedMemorySize, SMEM_TOT2);
    cudaFuncSetAttribute(attn_time_hmma,
                         cudaFuncAttributeMaxDynamicSharedMemorySize, AT_SMEM);

    int nx = Bv * Tv * Dv;
    split_f32<<<(nx + 255) / 256, 256>>>(x, xh, xl, nx);
    int tot1 = 3 * Dv * Dv;
    repack_wsplit<<<(tot1 + 255) / 256, 256>>>(w11, wqh, wql, Dv);
    repack_wsplit<<<(tot1 + 255) / 256, 256>>>(w12, wkh, wkl, Dv);
    repack_wsplit<<<(tot1 + 255) / 256, 256>>>(w13, wvh, wvl, Dv);
    int tot2 = 3 * D2v * Dv;
    repack_wsplit<<<(tot2 + 255) / 256, 256>>>(w2, w2h, w2l, D2v);

    // fused Q/K/V conv: grid z = b + 8*which
    conv_mma2<Dv, true><<<dim3(Tv / 256, Dv / 128, 3 * Bv), 256, SMEM_TOT2>>>(
        xh, xl,
        wqh, wql, wkh, wkl, wvh, wvl,
        b11, b12, b13,
        qh, ql, kh, kl, vh, vl,
        nullptr);

    attn_time_hmma<<<dim3(Tv / 128, Hv, Bv), 256, AT_SMEM>>>(qh, ql, kh, kl, vh, vl,
                                                             valh, vall);
    attn_chan_s<<<dim3(Hv, Bv), 256>>>(qh, ql, kh, kl, chanA);
    attn_chan_av<<<dim3(Hv, Bv, 4), 256>>>(vh, vl, chanA, valh, vall);

    conv_mma2<D2v, false><<<dim3(Tv / 256, Dv / 128, Bv), 256, SMEM_TOT2>>>(
        valh, vall,
        w2h, w2l, nullptr, nullptr, nullptr, nullptr,
        b2, nullptr, nullptr,
        nullptr, nullptr, nullptr, nullptr, nullptr, nullptr,
        out);
}